// round 9
// baseline (speedup 1.0000x reference)
#include <cuda_runtime.h>

#define N_NODES 50000
#define N_EDGES 600000
#define D 128
#define NLAYERS 5
#define NT 391                    // ceil(50000/128) row tiles of 128
#define SCAN_BLOCKS 196           // ceil(50000/256)

typedef unsigned long long ull;
typedef unsigned int u32;

// ----------------- persistent device scratch -----------------
__device__ float g_h[N_NODES * D];
__device__ float g_z[NT * 128 * D];
__device__ float g_out[N_NODES * D];
__device__ float g_etab[9 * D];
__device__ float g_stats[2 * D];
__device__ float g_aff[2 * D];
__device__ int   g_deg[N_NODES];
__device__ int   g_off[N_NODES + 1];
__device__ int   g_cur[N_NODES];
__device__ int   g_csr[N_EDGES];
__device__ int   g_bsum[SCAN_BLOCKS];
__device__ int   g_boff[SCAN_BLOCKS + 1];
__device__ int   g_is64;
// hidden activations per tile: [row(128)][colpair(128)] ull = (hi_u32 | lo_u32<<32)
__device__ __align__(16) unsigned char g_hid[(size_t)NT * 131072];
// weight images: [n][k] bf16, hi plane then lo plane (65536B each)
__device__ __align__(16) unsigned char g_w1T[131072];   // n=256, k=128
__device__ __align__(16) unsigned char g_w2T[131072];   // n=128, k=256

// ----------------- helpers -----------------
__device__ __forceinline__ u32 smem_u32(const void* p) {
    u32 a;
    asm("{ .reg .u64 t; cvta.to.shared.u64 t, %1; cvt.u32.u64 %0, t; }" : "=r"(a) : "l"(p));
    return a;
}
// split two floats into hi-pair / lo-pair bf16x2 words (x0 -> low half)
__device__ __forceinline__ void split2(float x0, float x1, u32& hp, u32& lp) {
    asm("cvt.rn.bf16x2.f32 %0, %1, %2;" : "=r"(hp) : "f"(x1), "f"(x0));
    float h0 = __uint_as_float(hp << 16);
    float h1 = __uint_as_float(hp & 0xffff0000u);
    float r0 = x0 - h0, r1 = x1 - h1;
    asm("cvt.rn.bf16x2.f32 %0, %1, %2;" : "=r"(lp) : "f"(r1), "f"(r0));
}
__device__ __forceinline__ void ldsm4(u32 addr, u32& r0, u32& r1, u32& r2, u32& r3) {
    asm volatile("ldmatrix.sync.aligned.m8n8.x4.shared.b16 {%0,%1,%2,%3}, [%4];"
                 : "=r"(r0), "=r"(r1), "=r"(r2), "=r"(r3) : "r"(addr));
}
__device__ __forceinline__ void mma16816(float* c, u32 a0, u32 a1, u32 a2, u32 a3,
                                         u32 b0, u32 b1) {
    asm volatile(
        "mma.sync.aligned.m16n8k16.row.col.f32.bf16.bf16.f32 "
        "{%0,%1,%2,%3}, {%4,%5,%6,%7}, {%8,%9}, {%0,%1,%2,%3};"
        : "+f"(c[0]), "+f"(c[1]), "+f"(c[2]), "+f"(c[3])
        : "r"(a0), "r"(a1), "r"(a2), "r"(a3), "r"(b0), "r"(b1));
}

__device__ __forceinline__ int getidx(const int* __restrict__ p, int i) {
    return g_is64 ? p[2 * i] : p[i];
}

// ----------------- merged setup: detect + etab + zero(deg,stats) ------------
__global__ void k_init(const int* __restrict__ x,
                       const float* __restrict__ bt,
                       const float* __restrict__ bd) {
    int i = blockIdx.x * blockDim.x + threadIdx.x;
    if (i < N_NODES) g_deg[i] = 0;
    if (blockIdx.x == 0 && threadIdx.x < 256) g_stats[threadIdx.x] = 0.f;
    if (blockIdx.x == 1 && threadIdx.x == 0) {
        int nz = 0;
        for (int j = 1; j < 128; j += 2) nz |= x[j];
        g_is64 = (nz == 0) ? 1 : 0;
    }
    if (blockIdx.x >= 2 && blockIdx.x < 11 && threadIdx.x < 128) {
        int code = blockIdx.x - 2, t = code / 3, d = code % 3, c = threadIdx.x;
        g_etab[code * D + c] = bt[t * D + c] + bd[d * D + c];
    }
}

__global__ void k_embed(const int* __restrict__ x,
                        const float* __restrict__ elem,
                        const float* __restrict__ chir) {
    int i = blockIdx.x * blockDim.x + threadIdx.x;
    if (i >= N_NODES * 32) return;
    int node = i >> 5, l = i & 31;
    int a = getidx(x, 2 * node);
    int c = getidx(x, 2 * node + 1);
    float4 va = __ldg((const float4*)(elem + a * D) + l);
    float4 vc = __ldg((const float4*)(chir + c * D) + l);
    ((float4*)(g_h + node * D))[l] =
        make_float4(va.x + vc.x, va.y + vc.y, va.z + vc.z, va.w + vc.w);
}

__global__ void k_hist(const int* __restrict__ ei) {
    int e = blockIdx.x * blockDim.x + threadIdx.x;
    if (e < N_EDGES) atomicAdd(&g_deg[getidx(ei, N_EDGES + e)], 1);
}

// ----------------- multi-block exclusive scan of g_deg -> g_off -------------
__global__ void k_scan1() {        // per-block reduce
    __shared__ int sh[256];
    int tid = threadIdx.x;
    int i = blockIdx.x * 256 + tid;
    int v = (i < N_NODES) ? g_deg[i] : 0;
    sh[tid] = v;
    __syncthreads();
    for (int off = 128; off > 0; off >>= 1) {
        if (tid < off) sh[tid] += sh[tid + off];
        __syncthreads();
    }
    if (tid == 0) g_bsum[blockIdx.x] = sh[0];
}

__global__ void k_scan2() {        // single-block scan of SCAN_BLOCKS sums
    __shared__ int sh[256];
    int tid = threadIdx.x;
    int v = (tid < SCAN_BLOCKS) ? g_bsum[tid] : 0;
    sh[tid] = v;
    __syncthreads();
    for (int off = 1; off < 256; off <<= 1) {
        int t = (tid >= off) ? sh[tid - off] : 0;
        __syncthreads();
        sh[tid] += t;
        __syncthreads();
    }
    if (tid < SCAN_BLOCKS) g_boff[tid] = sh[tid] - v;   // exclusive
    if (tid == SCAN_BLOCKS - 1) g_boff[SCAN_BLOCKS] = sh[tid];
}

__global__ void k_scan3() {        // local scan + block offset
    __shared__ int sh[256];
    int tid = threadIdx.x;
    int i = blockIdx.x * 256 + tid;
    int v = (i < N_NODES) ? g_deg[i] : 0;
    sh[tid] = v;
    __syncthreads();
    for (int off = 1; off < 256; off <<= 1) {
        int t = (tid >= off) ? sh[tid - off] : 0;
        __syncthreads();
        sh[tid] += t;
        __syncthreads();
    }
    int base = g_boff[blockIdx.x];
    if (i < N_NODES) {
        int ex = base + sh[tid] - v;
        g_off[i] = ex;
        g_cur[i] = ex;
    }
    if (i == N_NODES - 1 || (blockIdx.x == SCAN_BLOCKS - 1 && tid == 255))
        g_off[N_NODES] = g_boff[SCAN_BLOCKS];
}

__global__ void k_fill(const int* __restrict__ ei, const int* __restrict__ ea) {
    int e = blockIdx.x * blockDim.x + threadIdx.x;
    if (e < N_EDGES) {
        int src = getidx(ei, e);
        int dst = getidx(ei, N_EDGES + e);
        int t = getidx(ea, 2 * e);
        int d = getidx(ea, 2 * e + 1);
        int pos = atomicAdd(&g_cur[dst], 1);
        g_csr[pos] = src | ((t * 3 + d) << 20);
    }
}

// weight images: B[n][k] = W[k][n], split bf16 hi/lo planes
__global__ void k_prep(const float* __restrict__ W1, const float* __restrict__ W2) {
    int idx = blockIdx.x * blockDim.x + threadIdx.x;
    if (idx < 16384) {                        // W1: n 0..255, k pairs 0..63
        int n = idx >> 6, kp = idx & 63, k = kp * 2;
        float a = __ldg(W1 + k * 256 + n);
        float b = __ldg(W1 + (k + 1) * 256 + n);
        u32 hp, lp; split2(a, b, hp, lp);
        ((u32*)g_w1T)[n * 64 + kp] = hp;
        ((u32*)g_w1T)[16384 + n * 64 + kp] = lp;
    } else if (idx < 32768) {                 // W2: n 0..127, k pairs 0..127
        int q = idx - 16384;
        int n = q >> 7, kp = q & 127, k = kp * 2;
        float a = __ldg(W2 + k * 128 + n);
        float b = __ldg(W2 + (k + 1) * 128 + n);
        u32 hp, lp; split2(a, b, hp, lp);
        ((u32*)g_w2T)[n * 128 + kp] = hp;
        ((u32*)g_w2T)[16384 + n * 128 + kp] = lp;
    }
}

// ----------------- aggregation: one warp per dst node -----------------
__device__ __forceinline__ void agg_one(float4& acc, float4 hv, const float* et,
                                        int code, int c0, int mode,
                                        float4 sc, float4 sf) {
    if (mode) {
        hv.x = fmaxf(fmaf(hv.x, sc.x, sf.x), 0.f);
        hv.y = fmaxf(fmaf(hv.y, sc.y, sf.y), 0.f);
        hv.z = fmaxf(fmaf(hv.z, sc.z, sf.z), 0.f);
        hv.w = fmaxf(fmaf(hv.w, sc.w, sf.w), 0.f);
    }
    float4 ev = *(const float4*)(et + code * D + c0);
    acc.x += fmaxf(hv.x + ev.x, 0.f);
    acc.y += fmaxf(hv.y + ev.y, 0.f);
    acc.z += fmaxf(hv.z + ev.z, 0.f);
    acc.w += fmaxf(hv.w + ev.w, 0.f);
}

__global__ void __launch_bounds__(256) k_agg(int layer) {
    __shared__ float et[9 * D];
    __shared__ float aff[2 * D];
    int tid = threadIdx.x;
    for (int i = tid; i < 9 * D; i += 256) et[i] = g_etab[i];
    if (tid < 2 * D) aff[tid] = g_aff[tid];
    __syncthreads();

    const int mode = (layer > 0);
    const float* __restrict__ in = mode ? g_out : g_h;

    int warp = tid >> 5, lane = tid & 31;
    int node = blockIdx.x * 8 + warp;
    if (node >= N_NODES) return;
    int c0 = lane * 4;

    float4 sc = make_float4(1.f, 1.f, 1.f, 1.f);
    float4 sf = make_float4(0.f, 0.f, 0.f, 0.f);
    if (mode) { sc = *(float4*)&aff[c0]; sf = *(float4*)&aff[D + c0]; }

    int beg = g_off[node], end = g_off[node + 1];
    float4 acc = make_float4(0.f, 0.f, 0.f, 0.f);

    int e = beg;
    for (; e + 4 <= end; e += 4) {
        int v0 = __ldg(g_csr + e);
        int v1 = __ldg(g_csr + e + 1);
        int v2 = __ldg(g_csr + e + 2);
        int v3 = __ldg(g_csr + e + 3);
        float4 h0 = __ldg((const float4*)(in + (size_t)(v0 & 0xFFFFF) * D) + lane);
        float4 h1 = __ldg((const float4*)(in + (size_t)(v1 & 0xFFFFF) * D) + lane);
        float4 h2 = __ldg((const float4*)(in + (size_t)(v2 & 0xFFFFF) * D) + lane);
        float4 h3 = __ldg((const float4*)(in + (size_t)(v3 & 0xFFFFF) * D) + lane);
        agg_one(acc, h0, et, v0 >> 20, c0, mode, sc, sf);
        agg_one(acc, h1, et, v1 >> 20, c0, mode, sc, sf);
        agg_one(acc, h2, et, v2 >> 20, c0, mode, sc, sf);
        agg_one(acc, h3, et, v3 >> 20, c0, mode, sc, sf);
    }
    for (; e < end; e++) {
        int v = __ldg(g_csr + e);
        float4 hv = __ldg((const float4*)(in + (size_t)(v & 0xFFFFF) * D) + lane);
        agg_one(acc, hv, et, v >> 20, c0, mode, sc, sf);
    }

    float4 hd = __ldg((const float4*)(in + (size_t)node * D) + lane);
    if (mode) {
        hd.x = fmaxf(fmaf(hd.x, sc.x, sf.x), 0.f);
        hd.y = fmaxf(fmaf(hd.y, sc.y, sf.y), 0.f);
        hd.z = fmaxf(fmaf(hd.z, sc.z, sf.z), 0.f);
        hd.w = fmaxf(fmaf(hd.w, sc.w, sf.w), 0.f);
    }
    acc.x += hd.x; acc.y += hd.y; acc.z += hd.z; acc.w += hd.w;
    *(float4*)(g_z + (size_t)node * D + c0) = acc;
}

// ----------------- GEMM1: hidden = relu(z@W1+b1) -> interleaved hi/lo -------
// smem: B hi/lo [256][272B], A hi/lo [128][272B], bias[256]
#define KA_B_HI 0
#define KA_B_LO 69632
#define KA_A_HI 139264
#define KA_A_LO 174080
#define KA_BIAS 208896
#define KA_SMEM 209920

__global__ void __launch_bounds__(512, 1) kA(const float* __restrict__ b1) {
    extern __shared__ char sm[];
    u32 sb = smem_u32(sm);
    const int tid = threadIdx.x;
    const int warp = tid >> 5, lane = tid & 31;

    // stage weights (once) + bias
    {
        const uint4* src = (const uint4*)g_w1T;
        for (int i = tid; i < 8192; i += 512) {
            int p = i >> 12, r = (i >> 4) & 255, w = i & 15;
            *(uint4*)(sm + KA_B_HI + p * 69632 + r * 272 + w * 16) =
                src[p * 4096 + r * 16 + w];
        }
        if (tid < 256) ((float*)(sm + KA_BIAS))[tid] = __ldg(b1 + tid);
    }
    __syncthreads();

    const int wr = warp >> 2, wc = warp & 3;        // 4 x 4 warp grid, 32x64 tiles
    const u32 aHi = sb + KA_A_HI + (wr * 32 + (lane & 15)) * 272 + (lane >> 4) * 16;
    const u32 aLo = aHi + (KA_A_LO - KA_A_HI);
    const u32 bHi = sb + KA_B_HI + (wc * 64 + (lane & 15)) * 272 + (lane >> 4) * 16;
    const u32 bLo = bHi + 69632;
    const float* bias = (const float*)(sm + KA_BIAS);

    for (int tile = blockIdx.x; tile < NT; tile += gridDim.x) {
        // stage A: z fp32 -> split bf16 hi/lo
        for (int i = tid; i < 4096; i += 512) {
            int r = i >> 5, c4 = i & 31;
            int row = tile * 128 + r;
            float4 v = make_float4(0.f, 0.f, 0.f, 0.f);
            if (row < N_NODES) v = __ldg((const float4*)(g_z + (size_t)row * D) + c4);
            u32 h0, l0, h1, l1;
            split2(v.x, v.y, h0, l0);
            split2(v.z, v.w, h1, l1);
            *(ull*)(sm + KA_A_HI + r * 272 + c4 * 8) = (ull)h0 | ((ull)h1 << 32);
            *(ull*)(sm + KA_A_LO + r * 272 + c4 * 8) = (ull)l0 | ((ull)l1 << 32);
        }
        __syncthreads();

        float acc[2][8][4];
#pragma unroll
        for (int a = 0; a < 2; a++)
#pragma unroll
            for (int b = 0; b < 8; b++)
#pragma unroll
                for (int c = 0; c < 4; c++) acc[a][b][c] = 0.f;

        for (int ks = 0; ks < 8; ks++) {
            const u32 ko = ks * 32;
            u32 ah[2][4], al[2][4];
#pragma unroll
            for (int mt = 0; mt < 2; mt++) {
                ldsm4(aHi + mt * (16 * 272) + ko, ah[mt][0], ah[mt][1], ah[mt][2], ah[mt][3]);
                ldsm4(aLo + mt * (16 * 272) + ko, al[mt][0], al[mt][1], al[mt][2], al[mt][3]);
            }
#pragma unroll
            for (int g = 0; g < 4; g++) {
                u32 bh0, bh1, bh2, bh3, bl0, bl1, bl2, bl3;
                ldsm4(bHi + g * (16 * 272) + ko, bh0, bh1, bh2, bh3);
                ldsm4(bLo + g * (16 * 272) + ko, bl0, bl1, bl2, bl3);
#pragma unroll
                for (int mt = 0; mt < 2; mt++) {
                    mma16816(acc[mt][2 * g],     ah[mt][0], ah[mt][1], ah[mt][2], ah[mt][3], bh0, bh2);
                    mma16816(acc[mt][2 * g + 1], ah[mt][0], ah[mt][1], ah[mt][2], ah[mt][3], bh1, bh3);
                    mma16816(acc[mt][2 * g],     ah[mt][0], ah[mt][1], ah[mt][2], ah[mt][3], bl0, bl2);
                    mma16816(acc[mt][2 * g + 1], ah[mt][0], ah[mt][1], ah[mt][2], ah[mt][3], bl1, bl3);
                    mma16816(acc[mt][2 * g],     al[mt][0], al[mt][1], al[mt][2], al[mt][3], bh0, bh2);
                    mma16816(acc[mt][2 * g + 1], al[mt][0], al[mt][1], al[mt][2], al[mt][3], bh1, bh3);
                }
            }
        }

        // epilogue: bias + relu + re-split -> interleaved (hi,lo) ull stores
        ull* hid64 = (ull*)(g_hid + (size_t)tile * 131072);
        const int m0 = wr * 32, n0 = wc * 64;
#pragma unroll
        for (int mt = 0; mt < 2; mt++)
#pragma unroll
            for (int nt = 0; nt < 8; nt++) {
                int col = n0 + nt * 8 + 2 * (lane & 3);
                int r0 = m0 + mt * 16 + (lane >> 2);
                float bv0 = bias[col], bv1 = bias[col + 1];
                u32 hp, lp;
                float v0 = fmaxf(acc[mt][nt][0] + bv0, 0.f);
                float v1 = fmaxf(acc[mt][nt][1] + bv1, 0.f);
                split2(v0, v1, hp, lp);
                hid64[r0 * 128 + (col >> 1)] = (ull)hp | ((ull)lp << 32);
                v0 = fmaxf(acc[mt][nt][2] + bv0, 0.f);
                v1 = fmaxf(acc[mt][nt][3] + bv1, 0.f);
                split2(v0, v1, hp, lp);
                hid64[(r0 + 8) * 128 + (col >> 1)] = (ull)hp | ((ull)lp << 32);
            }
        __syncthreads();
    }
}

// ----------------- GEMM2: g_out = hidden @ W2 + b2, fused BN stats ----------
// smem: B hi/lo [128][528B], A hi/lo [128][272B] (half-K staged), bias[128]
#define KB_B_HI 0
#define KB_B_LO 67584
#define KB_A_HI 135168
#define KB_A_LO 169984
#define KB_BIAS 204800
#define KB_SMEM 205312

__global__ void __launch_bounds__(512, 1) kB(const float* __restrict__ b2) {
    extern __shared__ char sm[];
    u32 sb = smem_u32(sm);
    const int tid = threadIdx.x;
    const int warp = tid >> 5, lane = tid & 31;

    {
        const uint4* src = (const uint4*)g_w2T;
        for (int i = tid; i < 8192; i += 512) {
            int p = i >> 12, r = (i >> 5) & 127, w = i & 31;
            *(uint4*)(sm + KB_B_HI + p * 67584 + r * 528 + w * 16) =
                src[p * 4096 + r * 32 + w];
        }
        if (tid < 128) ((float*)(sm + KB_BIAS))[tid] = __ldg(b2 + tid);
    }
    __syncthreads();

    const int wr = warp >> 2, wc = warp & 3;        // 4 x 4 grid, 32x32 tiles
    const u32 aHi = sb + KB_A_HI + (wr * 32 + (lane & 15)) * 272 + (lane >> 4) * 16;
    const u32 aLo = aHi + (KB_A_LO - KB_A_HI);
    const u32 bHi = sb + KB_B_HI + (wc * 32 + (lane & 15)) * 528 + (lane >> 4) * 16;
    const u32 bLo = bHi + 67584;
    const float* bias = (const float*)(sm + KB_BIAS);

    // BN stat accumulators: this thread's columns are fixed across tiles
    float st_s[4][2], st_s2[4][2];
#pragma unroll
    for (int nt = 0; nt < 4; nt++) {
        st_s[nt][0] = st_s[nt][1] = 0.f;
        st_s2[nt][0] = st_s2[nt][1] = 0.f;
    }

    for (int tile = blockIdx.x; tile < NT; tile += gridDim.x) {
        float acc[2][4][4];
#pragma unroll
        for (int a = 0; a < 2; a++)
#pragma unroll
            for (int b = 0; b < 4; b++)
#pragma unroll
                for (int c = 0; c < 4; c++) acc[a][b][c] = 0.f;

        const ull* hid64 = (const ull*)(g_hid + (size_t)tile * 131072);
        for (int pass = 0; pass < 2; pass++) {
            // stage A half-K: de-interleave (hi,lo) ull -> hi/lo planes
            for (int i = tid; i < 8192; i += 512) {
                int r = i >> 6, cp = i & 63;
                ull v = __ldg(hid64 + r * 128 + pass * 64 + cp);
                *(u32*)(sm + KB_A_HI + r * 272 + cp * 4) = (u32)v;
                *(u32*)(sm + KB_A_LO + r * 272 + cp * 4) = (u32)(v >> 32);
            }
            __syncthreads();

            for (int ks = 0; ks < 8; ks++) {
                const u32 ko = ks * 32;
                const u32 bo = pass * 256 + ko;
                u32 ah[2][4], al[2][4];
#pragma unroll
                for (int mt = 0; mt < 2; mt++) {
                    ldsm4(aHi + mt * (16 * 272) + ko, ah[mt][0], ah[mt][1], ah[mt][2], ah[mt][3]);
                    ldsm4(aLo + mt * (16 * 272) + ko, al[mt][0], al[mt][1], al[mt][2], al[mt][3]);
                }
#pragma unroll
                for (int g = 0; g < 2; g++) {
                    u32 bh0, bh1, bh2, bh3, bl0, bl1, bl2, bl3;
                    ldsm4(bHi + g * (16 * 528) + bo, bh0, bh1, bh2, bh3);
                    ldsm4(bLo + g * (16 * 528) + bo, bl0, bl1, bl2, bl3);
#pragma unroll
                    for (int mt = 0; mt < 2; mt++) {
                        mma16816(acc[mt][2 * g],     ah[mt][0], ah[mt][1], ah[mt][2], ah[mt][3], bh0, bh2);
                        mma16816(acc[mt][2 * g + 1], ah[mt][0], ah[mt][1], ah[mt][2], ah[mt][3], bh1, bh3);
                        mma16816(acc[mt][2 * g],     ah[mt][0], ah[mt][1], ah[mt][2], ah[mt][3], bl0, bl2);
                        mma16816(acc[mt][2 * g + 1], ah[mt][0], ah[mt][1], ah[mt][2], ah[mt][3], bl1, bl3);
                        mma16816(acc[mt][2 * g],     al[mt][0], al[mt][1], al[mt][2], al[mt][3], bh0, bh2);
                        mma16816(acc[mt][2 * g + 1], al[mt][0], al[mt][1], al[mt][2], al[mt][3], bh1, bh3);
                    }
                }
            }
            __syncthreads();
        }

        // epilogue: bias, write fp32 g_out, accumulate BN stats in registers
        const int m0 = wr * 32, n0 = wc * 32;
#pragma unroll
        for (int mt = 0; mt < 2; mt++)
#pragma unroll
            for (int nt = 0; nt < 4; nt++) {
                int col = n0 + nt * 8 + 2 * (lane & 3);
                int r0 = tile * 128 + m0 + mt * 16 + (lane >> 2);
                float bv0 = bias[col], bv1 = bias[col + 1];
                if (r0 < N_NODES) {
                    float o0 = acc[mt][nt][0] + bv0;
                    float o1 = acc[mt][nt][1] + bv1;
                    *(float2*)(g_out + (size_t)r0 * D + col) = make_float2(o0, o1);
                    st_s[nt][0] += o0;  st_s2[nt][0] += o0 * o0;
                    st_s[nt][1] += o1;  st_s2[nt][1] += o1 * o1;
                }
                if (r0 + 8 < N_NODES) {
                    float o0 = acc[mt][nt][2] + bv0;
                    float o1 = acc[mt][nt][3] + bv1;
                    *(float2*)(g_out + (size_t)(r0 + 8) * D + col) = make_float2(o0, o1);
                    st_s[nt][0] += o0;  st_s2[nt][0] += o0 * o0;
                    st_s[nt][1] += o1;  st_s2[nt][1] += o1 * o1;
                }
            }
    }

    // reduce stats across the 8 lane-groups sharing columns (lane stride 4)
#pragma unroll
    for (int nt = 0; nt < 4; nt++)
#pragma unroll
        for (int p = 0; p < 2; p++) {
#pragma unroll
            for (int off = 16; off >= 4; off >>= 1) {
                st_s[nt][p]  += __shfl_xor_sync(0xffffffffu, st_s[nt][p],  off);
                st_s2[nt][p] += __shfl_xor_sync(0xffffffffu, st_s2[nt][p], off);
            }
        }
    if (lane < 4) {
        const int n0 = wc * 32;
#pragma unroll
        for (int nt = 0; nt < 4; nt++) {
            int col = n0 + nt * 8 + 2 * lane;
            atomicAdd(&g_stats[col],           st_s[nt][0]);
            atomicAdd(&g_stats[col + 1],       st_s[nt][1]);
            atomicAdd(&g_stats[128 + col],     st_s2[nt][0]);
            atomicAdd(&g_stats[128 + col + 1], st_s2[nt][1]);
        }
    }
}

// ----------------- BN fold: stats -> per-feature scale/shift, self-reset ----
__global__ void k_bnfold(const float* __restrict__ gamma, const float* __restrict__ beta) {
    int c = threadIdx.x;
    if (c < D) {
        float sum = g_stats[c], sum2 = g_stats[128 + c];
        const float invN = 1.0f / (float)N_NODES;
        float mean = sum * invN;
        float var = sum2 * invN - mean * mean;
        float scl = rsqrtf(var + 1e-5f) * __ldg(gamma + c);
        g_aff[c] = scl;
        g_aff[128 + c] = __ldg(beta + c) - mean * scl;
        g_stats[c] = 0.f;
        g_stats[128 + c] = 0.f;
    }
}

// ----------------- final: apply last BN (no relu) -> d_out ------------------
__global__ void k_final(float* __restrict__ out) {
    int i = blockIdx.x * blockDim.x + threadIdx.x;
    if (i >= N_NODES * 32) return;
    int c0 = (i & 31) * 4;
    float4 v = ((const float4*)g_out)[i];
    float4 sc = *(const float4*)&g_aff[c0];
    float4 sf = *(const float4*)&g_aff[D + c0];
    v.x = fmaf(v.x, sc.x, sf.x);
    v.y = fmaf(v.y, sc.y, sf.y);
    v.z = fmaf(v.z, sc.z, sf.z);
    v.w = fmaf(v.w, sc.w, sf.w);
    ((float4*)out)[i] = v;
}

// ----------------- launch -----------------
extern "C" void kernel_launch(void* const* d_in, const int* in_sizes, int n_in,
                              void* d_out, int out_size) {
    const int*   x    = (const int*)d_in[0];
    const int*   ei   = (const int*)d_in[1];
    const int*   ea   = (const int*)d_in[2];
    const float* elem = (const float*)d_in[3];
    const float* chir = (const float*)d_in[4];
    const float* bt   = (const float*)d_in[5];
    const float* bd   = (const float*)d_in[6];
    const float* W1   = (const float*)d_in[7];
    const float* b1   = (const float*)d_in[8];
    const float* W2   = (const float*)d_in[9];
    const float* b2   = (const float*)d_in[10];
    const float* bng  = (const float*)d_in[11];
    const float* bnb  = (const float*)d_in[12];
    float* out = (float*)d_out;

    static int attr_done = 0;
    if (!attr_done) {
        cudaFuncSetAttribute(kA, cudaFuncAttributeMaxDynamicSharedMemorySize, KA_SMEM);
        cudaFuncSetAttribute(kB, cudaFuncAttributeMaxDynamicSharedMemorySize, KB_SMEM);
        attr_done = 1;
    }

    k_init<<<(N_NODES + 255) / 256, 256>>>(x, bt, bd);
    k_embed<<<(N_NODES * 32 + 255) / 256, 256>>>(x, elem, chir);
    k_hist<<<(N_EDGES + 255) / 256, 256>>>(ei);
    k_scan1<<<SCAN_BLOCKS, 256>>>();
    k_scan2<<<1, 256>>>();
    k_scan3<<<SCAN_BLOCKS, 256>>>();
    k_fill<<<(N_EDGES + 255) / 256, 256>>>(ei, ea);
    k_prep<<<128, 256>>>(W1, W2);

    for (int l = 0; l < NLAYERS; l++) {
        k_agg<<<(N_NODES + 7) / 8, 256>>>(l);
        kA<<<148, 512, KA_SMEM>>>(b1);
        kB<<<148, 512, KB_SMEM>>>(b2);
        k_bnfold<<<1, 128>>>(bng + l * D, bnb + l * D);
    }
    k_final<<<(N_NODES * 32 + 255) / 256, 256>>>(out);
}

// round 10
// speedup vs baseline: 1.3746x; 1.3746x over previous
#include <cuda_runtime.h>

#define N_NODES 50000
#define N_EDGES 600000
#define D 128
#define NLAYERS 5
#define NT 391                    // ceil(50000/128) row tiles of 128
#define SCAN_BLOCKS 196           // ceil(50000/256)

typedef unsigned long long ull;
typedef unsigned int u32;

// ----------------- persistent device scratch -----------------
__device__ float g_h[N_NODES * D];
__device__ float g_out[N_NODES * D];
__device__ float g_etab[9 * D];
__device__ float g_stats[2 * D];
__device__ float g_aff[2 * D];
__device__ int   g_deg[N_NODES];
__device__ int   g_off[N_NODES + 1];
__device__ int   g_cur[N_NODES];
__device__ int   g_csr[N_EDGES];
__device__ int   g_bsum[SCAN_BLOCKS];
__device__ int   g_boff[SCAN_BLOCKS + 1];
__device__ int   g_is64;
// hidden activations per tile: [row(128)][colpair(128)] ull = (hi_u32 | lo_u32<<32)
__device__ __align__(16) unsigned char g_hid[(size_t)NT * 131072];
// weight images: [n][k] bf16, hi plane then lo plane (65536B each)
__device__ __align__(16) unsigned char g_w1T[131072];   // n=256, k=128
__device__ __align__(16) unsigned char g_w2T[131072];   // n=128, k=256

// ----------------- helpers -----------------
__device__ __forceinline__ u32 smem_u32(const void* p) {
    u32 a;
    asm("{ .reg .u64 t; cvta.to.shared.u64 t, %1; cvt.u32.u64 %0, t; }" : "=r"(a) : "l"(p));
    return a;
}
// split two floats into hi-pair / lo-pair bf16x2 words (x0 -> low half)
__device__ __forceinline__ void split2(float x0, float x1, u32& hp, u32& lp) {
    asm("cvt.rn.bf16x2.f32 %0, %1, %2;" : "=r"(hp) : "f"(x1), "f"(x0));
    float h0 = __uint_as_float(hp << 16);
    float h1 = __uint_as_float(hp & 0xffff0000u);
    float r0 = x0 - h0, r1 = x1 - h1;
    asm("cvt.rn.bf16x2.f32 %0, %1, %2;" : "=r"(lp) : "f"(r1), "f"(r0));
}
__device__ __forceinline__ void ldsm4(u32 addr, u32& r0, u32& r1, u32& r2, u32& r3) {
    asm volatile("ldmatrix.sync.aligned.m8n8.x4.shared.b16 {%0,%1,%2,%3}, [%4];"
                 : "=r"(r0), "=r"(r1), "=r"(r2), "=r"(r3) : "r"(addr));
}
__device__ __forceinline__ void mma16816(float* c, u32 a0, u32 a1, u32 a2, u32 a3,
                                         u32 b0, u32 b1) {
    asm volatile(
        "mma.sync.aligned.m16n8k16.row.col.f32.bf16.bf16.f32 "
        "{%0,%1,%2,%3}, {%4,%5,%6,%7}, {%8,%9}, {%0,%1,%2,%3};"
        : "+f"(c[0]), "+f"(c[1]), "+f"(c[2]), "+f"(c[3])
        : "r"(a0), "r"(a1), "r"(a2), "r"(a3), "r"(b0), "r"(b1));
}

__device__ __forceinline__ int getidx(const int* __restrict__ p, int i) {
    return g_is64 ? p[2 * i] : p[i];
}

// ----------------- merged setup: detect + etab + zero(deg,stats) ------------
__global__ void k_init(const int* __restrict__ x,
                       const float* __restrict__ bt,
                       const float* __restrict__ bd) {
    int i = blockIdx.x * blockDim.x + threadIdx.x;
    if (i < N_NODES) g_deg[i] = 0;
    if (blockIdx.x == 0 && threadIdx.x < 256) g_stats[threadIdx.x] = 0.f;
    if (blockIdx.x == 1 && threadIdx.x == 0) {
        int nz = 0;
        for (int j = 1; j < 128; j += 2) nz |= x[j];
        g_is64 = (nz == 0) ? 1 : 0;
    }
    if (blockIdx.x >= 2 && blockIdx.x < 11 && threadIdx.x < 128) {
        int code = blockIdx.x - 2, t = code / 3, d = code % 3, c = threadIdx.x;
        g_etab[code * D + c] = bt[t * D + c] + bd[d * D + c];
    }
}

__global__ void k_embed(const int* __restrict__ x,
                        const float* __restrict__ elem,
                        const float* __restrict__ chir) {
    int i = blockIdx.x * blockDim.x + threadIdx.x;
    if (i >= N_NODES * 32) return;
    int node = i >> 5, l = i & 31;
    int a = getidx(x, 2 * node);
    int c = getidx(x, 2 * node + 1);
    float4 va = __ldg((const float4*)(elem + a * D) + l);
    float4 vc = __ldg((const float4*)(chir + c * D) + l);
    ((float4*)(g_h + node * D))[l] =
        make_float4(va.x + vc.x, va.y + vc.y, va.z + vc.z, va.w + vc.w);
}

__global__ void k_hist(const int* __restrict__ ei) {
    int e = blockIdx.x * blockDim.x + threadIdx.x;
    if (e < N_EDGES) atomicAdd(&g_deg[getidx(ei, N_EDGES + e)], 1);
}

// ----------------- multi-block exclusive scan of g_deg -> g_off -------------
__global__ void k_scan1() {        // per-block reduce
    __shared__ int sh[256];
    int tid = threadIdx.x;
    int i = blockIdx.x * 256 + tid;
    int v = (i < N_NODES) ? g_deg[i] : 0;
    sh[tid] = v;
    __syncthreads();
    for (int off = 128; off > 0; off >>= 1) {
        if (tid < off) sh[tid] += sh[tid + off];
        __syncthreads();
    }
    if (tid == 0) g_bsum[blockIdx.x] = sh[0];
}

__global__ void k_scan2() {        // single-block scan of SCAN_BLOCKS sums
    __shared__ int sh[256];
    int tid = threadIdx.x;
    int v = (tid < SCAN_BLOCKS) ? g_bsum[tid] : 0;
    sh[tid] = v;
    __syncthreads();
    for (int off = 1; off < 256; off <<= 1) {
        int t = (tid >= off) ? sh[tid - off] : 0;
        __syncthreads();
        sh[tid] += t;
        __syncthreads();
    }
    if (tid < SCAN_BLOCKS) g_boff[tid] = sh[tid] - v;   // exclusive
    if (tid == SCAN_BLOCKS - 1) g_boff[SCAN_BLOCKS] = sh[tid];
}

__global__ void k_scan3() {        // local scan + block offset
    __shared__ int sh[256];
    int tid = threadIdx.x;
    int i = blockIdx.x * 256 + tid;
    int v = (i < N_NODES) ? g_deg[i] : 0;
    sh[tid] = v;
    __syncthreads();
    for (int off = 1; off < 256; off <<= 1) {
        int t = (tid >= off) ? sh[tid - off] : 0;
        __syncthreads();
        sh[tid] += t;
        __syncthreads();
    }
    int base = g_boff[blockIdx.x];
    if (i < N_NODES) {
        int ex = base + sh[tid] - v;
        g_off[i] = ex;
        g_cur[i] = ex;
    }
    if (i == N_NODES - 1 || (blockIdx.x == SCAN_BLOCKS - 1 && tid == 255))
        g_off[N_NODES] = g_boff[SCAN_BLOCKS];
}

__global__ void k_fill(const int* __restrict__ ei, const int* __restrict__ ea) {
    int e = blockIdx.x * blockDim.x + threadIdx.x;
    if (e < N_EDGES) {
        int src = getidx(ei, e);
        int dst = getidx(ei, N_EDGES + e);
        int t = getidx(ea, 2 * e);
        int d = getidx(ea, 2 * e + 1);
        int pos = atomicAdd(&g_cur[dst], 1);
        g_csr[pos] = src | ((t * 3 + d) << 20);
    }
}

// weight images: B[n][k] = W[k][n], split bf16 hi/lo planes
__global__ void k_prep(const float* __restrict__ W1, const float* __restrict__ W2) {
    int idx = blockIdx.x * blockDim.x + threadIdx.x;
    if (idx < 16384) {                        // W1: n 0..255, k pairs 0..63
        int n = idx >> 6, kp = idx & 63, k = kp * 2;
        float a = __ldg(W1 + k * 256 + n);
        float b = __ldg(W1 + (k + 1) * 256 + n);
        u32 hp, lp; split2(a, b, hp, lp);
        ((u32*)g_w1T)[n * 64 + kp] = hp;
        ((u32*)g_w1T)[16384 + n * 64 + kp] = lp;
    } else if (idx < 32768) {                 // W2: n 0..127, k pairs 0..127
        int q = idx - 16384;
        int n = q >> 7, kp = q & 127, k = kp * 2;
        float a = __ldg(W2 + k * 128 + n);
        float b = __ldg(W2 + (k + 1) * 128 + n);
        u32 hp, lp; split2(a, b, hp, lp);
        ((u32*)g_w2T)[n * 128 + kp] = hp;
        ((u32*)g_w2T)[16384 + n * 128 + kp] = lp;
    }
}

// ----------------- fused agg + GEMM1 ----------------------------------------
// smem: B hi/lo [256][272B], A hi/lo [128][272B], bias[256], etab[9*128]
#define KA_B_HI 0
#define KA_B_LO 69632
#define KA_A_HI 139264
#define KA_A_LO 174080
#define KA_BIAS 208896
#define KA_ETAB 209920
#define KA_SMEM 214528

__device__ __forceinline__ void agg_one(float4& acc, float4 hv, const float* et,
                                        int code, int c0, int mode,
                                        float4 sc, float4 sf) {
    if (mode) {
        hv.x = fmaxf(fmaf(hv.x, sc.x, sf.x), 0.f);
        hv.y = fmaxf(fmaf(hv.y, sc.y, sf.y), 0.f);
        hv.z = fmaxf(fmaf(hv.z, sc.z, sf.z), 0.f);
        hv.w = fmaxf(fmaf(hv.w, sc.w, sf.w), 0.f);
    }
    float4 ev = *(const float4*)(et + code * D + c0);
    acc.x += fmaxf(hv.x + ev.x, 0.f);
    acc.y += fmaxf(hv.y + ev.y, 0.f);
    acc.z += fmaxf(hv.z + ev.z, 0.f);
    acc.w += fmaxf(hv.w + ev.w, 0.f);
}

__global__ void __launch_bounds__(512, 1) kA(const float* __restrict__ b1, int layer) {
    extern __shared__ char sm[];
    u32 sb = smem_u32(sm);
    const int tid = threadIdx.x;
    const int warp = tid >> 5, lane = tid & 31;

    // stage weights + bias + etab (once)
    {
        const uint4* src = (const uint4*)g_w1T;
        for (int i = tid; i < 8192; i += 512) {
            int p = i >> 12, r = (i >> 4) & 255, w = i & 15;
            *(uint4*)(sm + KA_B_HI + p * 69632 + r * 272 + w * 16) =
                src[p * 4096 + r * 16 + w];
        }
        if (tid < 256) ((float*)(sm + KA_BIAS))[tid] = __ldg(b1 + tid);
        for (int i = tid; i < 9 * D; i += 512)
            ((float*)(sm + KA_ETAB))[i] = g_etab[i];
    }
    __syncthreads();

    const int mode = (layer > 0);
    const float* __restrict__ in = mode ? g_out : g_h;
    const float* et = (const float*)(sm + KA_ETAB);
    const int c0 = lane * 4;

    float4 sc = make_float4(1.f, 1.f, 1.f, 1.f);
    float4 sf = make_float4(0.f, 0.f, 0.f, 0.f);
    if (mode) {
        sc = *(const float4*)&g_aff[c0];
        sf = *(const float4*)&g_aff[D + c0];
    }

    const int wr = warp >> 2, wc = warp & 3;        // 4 x 4 warp grid, 32x64 tiles
    const u32 aHi = sb + KA_A_HI + (wr * 32 + (lane & 15)) * 272 + (lane >> 4) * 16;
    const u32 aLo = aHi + (KA_A_LO - KA_A_HI);
    const u32 bHi = sb + KA_B_HI + (wc * 64 + (lane & 15)) * 272 + (lane >> 4) * 16;
    const u32 bLo = bHi + 69632;
    const float* bias = (const float*)(sm + KA_BIAS);

    for (int tile = blockIdx.x; tile < NT; tile += gridDim.x) {
        // fused aggregation: each warp aggregates 8 nodes directly into smem A
#pragma unroll 1
        for (int r8 = 0; r8 < 8; r8++) {
            int r = warp * 8 + r8;
            int node = tile * 128 + r;
            float4 acc = make_float4(0.f, 0.f, 0.f, 0.f);
            if (node < N_NODES) {
                int beg = g_off[node], end = g_off[node + 1];
                int e = beg;
                for (; e + 4 <= end; e += 4) {
                    int v0 = __ldg(g_csr + e);
                    int v1 = __ldg(g_csr + e + 1);
                    int v2 = __ldg(g_csr + e + 2);
                    int v3 = __ldg(g_csr + e + 3);
                    float4 h0 = __ldg((const float4*)(in + (size_t)(v0 & 0xFFFFF) * D) + lane);
                    float4 h1 = __ldg((const float4*)(in + (size_t)(v1 & 0xFFFFF) * D) + lane);
                    float4 h2 = __ldg((const float4*)(in + (size_t)(v2 & 0xFFFFF) * D) + lane);
                    float4 h3 = __ldg((const float4*)(in + (size_t)(v3 & 0xFFFFF) * D) + lane);
                    agg_one(acc, h0, et, v0 >> 20, c0, mode, sc, sf);
                    agg_one(acc, h1, et, v1 >> 20, c0, mode, sc, sf);
                    agg_one(acc, h2, et, v2 >> 20, c0, mode, sc, sf);
                    agg_one(acc, h3, et, v3 >> 20, c0, mode, sc, sf);
                }
                for (; e < end; e++) {
                    int v = __ldg(g_csr + e);
                    float4 hv = __ldg((const float4*)(in + (size_t)(v & 0xFFFFF) * D) + lane);
                    agg_one(acc, hv, et, v >> 20, c0, mode, sc, sf);
                }
                float4 hd = __ldg((const float4*)(in + (size_t)node * D) + lane);
                if (mode) {
                    hd.x = fmaxf(fmaf(hd.x, sc.x, sf.x), 0.f);
                    hd.y = fmaxf(fmaf(hd.y, sc.y, sf.y), 0.f);
                    hd.z = fmaxf(fmaf(hd.z, sc.z, sf.z), 0.f);
                    hd.w = fmaxf(fmaf(hd.w, sc.w, sf.w), 0.f);
                }
                acc.x += hd.x; acc.y += hd.y; acc.z += hd.z; acc.w += hd.w;
            }
            u32 h0, l0, h1, l1;
            split2(acc.x, acc.y, h0, l0);
            split2(acc.z, acc.w, h1, l1);
            *(ull*)(sm + KA_A_HI + r * 272 + lane * 8) = (ull)h0 | ((ull)h1 << 32);
            *(ull*)(sm + KA_A_LO + r * 272 + lane * 8) = (ull)l0 | ((ull)l1 << 32);
        }
        __syncthreads();

        float acc[2][8][4];
#pragma unroll
        for (int a = 0; a < 2; a++)
#pragma unroll
            for (int b = 0; b < 8; b++)
#pragma unroll
                for (int c = 0; c < 4; c++) acc[a][b][c] = 0.f;

        for (int ks = 0; ks < 8; ks++) {
            const u32 ko = ks * 32;
            u32 ah[2][4], al[2][4];
#pragma unroll
            for (int mt = 0; mt < 2; mt++) {
                ldsm4(aHi + mt * (16 * 272) + ko, ah[mt][0], ah[mt][1], ah[mt][2], ah[mt][3]);
                ldsm4(aLo + mt * (16 * 272) + ko, al[mt][0], al[mt][1], al[mt][2], al[mt][3]);
            }
#pragma unroll
            for (int g = 0; g < 4; g++) {
                u32 bh0, bh1, bh2, bh3, bl0, bl1, bl2, bl3;
                ldsm4(bHi + g * (16 * 272) + ko, bh0, bh1, bh2, bh3);
                ldsm4(bLo + g * (16 * 272) + ko, bl0, bl1, bl2, bl3);
#pragma unroll
                for (int mt = 0; mt < 2; mt++) {
                    mma16816(acc[mt][2 * g],     ah[mt][0], ah[mt][1], ah[mt][2], ah[mt][3], bh0, bh2);
                    mma16816(acc[mt][2 * g + 1], ah[mt][0], ah[mt][1], ah[mt][2], ah[mt][3], bh1, bh3);
                    mma16816(acc[mt][2 * g],     ah[mt][0], ah[mt][1], ah[mt][2], ah[mt][3], bl0, bl2);
                    mma16816(acc[mt][2 * g + 1], ah[mt][0], ah[mt][1], ah[mt][2], ah[mt][3], bl1, bl3);
                    mma16816(acc[mt][2 * g],     al[mt][0], al[mt][1], al[mt][2], al[mt][3], bh0, bh2);
                    mma16816(acc[mt][2 * g + 1], al[mt][0], al[mt][1], al[mt][2], al[mt][3], bh1, bh3);
                }
            }
        }

        // epilogue: bias + relu + re-split -> interleaved (hi,lo) ull stores
        ull* hid64 = (ull*)(g_hid + (size_t)tile * 131072);
        const int m0 = wr * 32, n0 = wc * 64;
#pragma unroll
        for (int mt = 0; mt < 2; mt++)
#pragma unroll
            for (int nt = 0; nt < 8; nt++) {
                int col = n0 + nt * 8 + 2 * (lane & 3);
                int r0 = m0 + mt * 16 + (lane >> 2);
                float bv0 = bias[col], bv1 = bias[col + 1];
                u32 hp, lp;
                float v0 = fmaxf(acc[mt][nt][0] + bv0, 0.f);
                float v1 = fmaxf(acc[mt][nt][1] + bv1, 0.f);
                split2(v0, v1, hp, lp);
                hid64[r0 * 128 + (col >> 1)] = (ull)hp | ((ull)lp << 32);
                v0 = fmaxf(acc[mt][nt][2] + bv0, 0.f);
                v1 = fmaxf(acc[mt][nt][3] + bv1, 0.f);
                split2(v0, v1, hp, lp);
                hid64[(r0 + 8) * 128 + (col >> 1)] = (ull)hp | ((ull)lp << 32);
            }
        __syncthreads();
    }
}

// ----------------- GEMM2: g_out = hidden @ W2 + b2, fused BN stats ----------
// smem: B hi/lo [128][528B], A hi/lo [128][272B] (half-K staged), bias[128]
#define KB_B_HI 0
#define KB_B_LO 67584
#define KB_A_HI 135168
#define KB_A_LO 169984
#define KB_BIAS 204800
#define KB_SMEM 205312

__global__ void __launch_bounds__(512, 1) kB(const float* __restrict__ b2) {
    extern __shared__ char sm[];
    u32 sb = smem_u32(sm);
    const int tid = threadIdx.x;
    const int warp = tid >> 5, lane = tid & 31;

    {
        const uint4* src = (const uint4*)g_w2T;
        for (int i = tid; i < 8192; i += 512) {
            int p = i >> 12, r = (i >> 5) & 127, w = i & 31;
            *(uint4*)(sm + KB_B_HI + p * 67584 + r * 528 + w * 16) =
                src[p * 4096 + r * 32 + w];
        }
        if (tid < 128) ((float*)(sm + KB_BIAS))[tid] = __ldg(b2 + tid);
    }
    __syncthreads();

    const int wr = warp >> 2, wc = warp & 3;        // 4 x 4 grid, 32x32 tiles
    const u32 aHi = sb + KB_A_HI + (wr * 32 + (lane & 15)) * 272 + (lane >> 4) * 16;
    const u32 aLo = aHi + (KB_A_LO - KB_A_HI);
    const u32 bHi = sb + KB_B_HI + (wc * 32 + (lane & 15)) * 528 + (lane >> 4) * 16;
    const u32 bLo = bHi + 67584;
    const float* bias = (const float*)(sm + KB_BIAS);

    // BN stat accumulators: this thread's columns are fixed across tiles
    float st_s[4][2], st_s2[4][2];
#pragma unroll
    for (int nt = 0; nt < 4; nt++) {
        st_s[nt][0] = st_s[nt][1] = 0.f;
        st_s2[nt][0] = st_s2[nt][1] = 0.f;
    }

    for (int tile = blockIdx.x; tile < NT; tile += gridDim.x) {
        float acc[2][4][4];
#pragma unroll
        for (int a = 0; a < 2; a++)
#pragma unroll
            for (int b = 0; b < 4; b++)
#pragma unroll
                for (int c = 0; c < 4; c++) acc[a][b][c] = 0.f;

        const ull* hid64 = (const ull*)(g_hid + (size_t)tile * 131072);
        for (int pass = 0; pass < 2; pass++) {
            // stage A half-K: de-interleave (hi,lo) ull -> hi/lo planes
            for (int i = tid; i < 8192; i += 512) {
                int r = i >> 6, cp = i & 63;
                ull v = __ldg(hid64 + r * 128 + pass * 64 + cp);
                *(u32*)(sm + KB_A_HI + r * 272 + cp * 4) = (u32)v;
                *(u32*)(sm + KB_A_LO + r * 272 + cp * 4) = (u32)(v >> 32);
            }
            __syncthreads();

            for (int ks = 0; ks < 8; ks++) {
                const u32 ko = ks * 32;
                const u32 bo = pass * 256 + ko;
                u32 ah[2][4], al[2][4];
#pragma unroll
                for (int mt = 0; mt < 2; mt++) {
                    ldsm4(aHi + mt * (16 * 272) + ko, ah[mt][0], ah[mt][1], ah[mt][2], ah[mt][3]);
                    ldsm4(aLo + mt * (16 * 272) + ko, al[mt][0], al[mt][1], al[mt][2], al[mt][3]);
                }
#pragma unroll
                for (int g = 0; g < 2; g++) {
                    u32 bh0, bh1, bh2, bh3, bl0, bl1, bl2, bl3;
                    ldsm4(bHi + g * (16 * 528) + bo, bh0, bh1, bh2, bh3);
                    ldsm4(bLo + g * (16 * 528) + bo, bl0, bl1, bl2, bl3);
#pragma unroll
                    for (int mt = 0; mt < 2; mt++) {
                        mma16816(acc[mt][2 * g],     ah[mt][0], ah[mt][1], ah[mt][2], ah[mt][3], bh0, bh2);
                        mma16816(acc[mt][2 * g + 1], ah[mt][0], ah[mt][1], ah[mt][2], ah[mt][3], bh1, bh3);
                        mma16816(acc[mt][2 * g],     ah[mt][0], ah[mt][1], ah[mt][2], ah[mt][3], bl0, bl2);
                        mma16816(acc[mt][2 * g + 1], ah[mt][0], ah[mt][1], ah[mt][2], ah[mt][3], bl1, bl3);
                        mma16816(acc[mt][2 * g],     al[mt][0], al[mt][1], al[mt][2], al[mt][3], bh0, bh2);
                        mma16816(acc[mt][2 * g + 1], al[mt][0], al[mt][1], al[mt][2], al[mt][3], bh1, bh3);
                    }
                }
            }
            __syncthreads();
        }

        // epilogue: bias, write fp32 g_out, accumulate BN stats in registers
        const int m0 = wr * 32, n0 = wc * 32;
#pragma unroll
        for (int mt = 0; mt < 2; mt++)
#pragma unroll
            for (int nt = 0; nt < 4; nt++) {
                int col = n0 + nt * 8 + 2 * (lane & 3);
                int r0 = tile * 128 + m0 + mt * 16 + (lane >> 2);
                float bv0 = bias[col], bv1 = bias[col + 1];
                if (r0 < N_NODES) {
                    float o0 = acc[mt][nt][0] + bv0;
                    float o1 = acc[mt][nt][1] + bv1;
                    *(float2*)(g_out + (size_t)r0 * D + col) = make_float2(o0, o1);
                    st_s[nt][0] += o0;  st_s2[nt][0] += o0 * o0;
                    st_s[nt][1] += o1;  st_s2[nt][1] += o1 * o1;
                }
                if (r0 + 8 < N_NODES) {
                    float o0 = acc[mt][nt][2] + bv0;
                    float o1 = acc[mt][nt][3] + bv1;
                    *(float2*)(g_out + (size_t)(r0 + 8) * D + col) = make_float2(o0, o1);
                    st_s[nt][0] += o0;  st_s2[nt][0] += o0 * o0;
                    st_s[nt][1] += o1;  st_s2[nt][1] += o1 * o1;
                }
            }
    }

    // reduce stats across the 8 lane-groups sharing columns (lane stride 4)
#pragma unroll
    for (int nt = 0; nt < 4; nt++)
#pragma unroll
        for (int p = 0; p < 2; p++) {
#pragma unroll
            for (int off = 16; off >= 4; off >>= 1) {
                st_s[nt][p]  += __shfl_xor_sync(0xffffffffu, st_s[nt][p],  off);
                st_s2[nt][p] += __shfl_xor_sync(0xffffffffu, st_s2[nt][p], off);
            }
        }
    if (lane < 4) {
        const int n0 = wc * 32;
#pragma unroll
        for (int nt = 0; nt < 4; nt++) {
            int col = n0 + nt * 8 + 2 * lane;
            atomicAdd(&g_stats[col],           st_s[nt][0]);
            atomicAdd(&g_stats[col + 1],       st_s[nt][1]);
            atomicAdd(&g_stats[128 + col],     st_s2[nt][0]);
            atomicAdd(&g_stats[128 + col + 1], st_s2[nt][1]);
        }
    }
}

// ----------------- BN fold: stats -> per-feature scale/shift, self-reset ----
__global__ void k_bnfold(const float* __restrict__ gamma, const float* __restrict__ beta) {
    int c = threadIdx.x;
    if (c < D) {
        float sum = g_stats[c], sum2 = g_stats[128 + c];
        const float invN = 1.0f / (float)N_NODES;
        float mean = sum * invN;
        float var = sum2 * invN - mean * mean;
        float scl = rsqrtf(var + 1e-5f) * __ldg(gamma + c);
        g_aff[c] = scl;
        g_aff[128 + c] = __ldg(beta + c) - mean * scl;
        g_stats[c] = 0.f;
        g_stats[128 + c] = 0.f;
    }
}

// ----------------- final: apply last BN (no relu) -> d_out ------------------
__global__ void k_final(float* __restrict__ out) {
    int i = blockIdx.x * blockDim.x + threadIdx.x;
    if (i >= N_NODES * 32) return;
    int c0 = (i & 31) * 4;
    float4 v = ((const float4*)g_out)[i];
    float4 sc = *(const float4*)&g_aff[c0];
    float4 sf = *(const float4*)&g_aff[D + c0];
    v.x = fmaf(v.x, sc.x, sf.x);
    v.y = fmaf(v.y, sc.y, sf.y);
    v.z = fmaf(v.z, sc.z, sf.z);
    v.w = fmaf(v.w, sc.w, sf.w);
    ((float4*)out)[i] = v;
}

// ----------------- launch -----------------
extern "C" void kernel_launch(void* const* d_in, const int* in_sizes, int n_in,
                              void* d_out, int out_size) {
    const int*   x    = (const int*)d_in[0];
    const int*   ei   = (const int*)d_in[1];
    const int*   ea   = (const int*)d_in[2];
    const float* elem = (const float*)d_in[3];
    const float* chir = (const float*)d_in[4];
    const float* bt   = (const float*)d_in[5];
    const float* bd   = (const float*)d_in[6];
    const float* W1   = (const float*)d_in[7];
    const float* b1   = (const float*)d_in[8];
    const float* W2   = (const float*)d_in[9];
    const float* b2   = (const float*)d_in[10];
    const float* bng  = (const float*)d_in[11];
    const float* bnb  = (const float*)d_in[12];
    float* out = (float*)d_out;

    static int attr_done = 0;
    if (!attr_done) {
        cudaFuncSetAttribute(kA, cudaFuncAttributeMaxDynamicSharedMemorySize, KA_SMEM);
        cudaFuncSetAttribute(kB, cudaFuncAttributeMaxDynamicSharedMemorySize, KB_SMEM);
        attr_done = 1;
    }

    k_init<<<(N_NODES + 255) / 256, 256>>>(x, bt, bd);
    k_embed<<<(N_NODES * 32 + 255) / 256, 256>>>(x, elem, chir);
    k_hist<<<(N_EDGES + 255) / 256, 256>>>(ei);
    k_scan1<<<SCAN_BLOCKS, 256>>>();
    k_scan2<<<1, 256>>>();
    k_scan3<<<SCAN_BLOCKS, 256>>>();
    k_fill<<<(N_EDGES + 255) / 256, 256>>>(ei, ea);
    k_prep<<<128, 256>>>(W1, W2);

    for (int l = 0; l < NLAYERS; l++) {
        kA<<<148, 512, KA_SMEM>>>(b1, l);
        kB<<<148, 512, KB_SMEM>>>(b2);
        k_bnfold<<<1, 128>>>(bng + l * D, bnb + l * D);
    }
    k_final<<<(N_NODES * 32 + 255) / 256, 256>>>(out);
}

// round 12
// speedup vs baseline: 1.4236x; 1.0356x over previous
#include <cuda_runtime.h>

#define N_NODES 50000
#define N_EDGES 600000
#define D 128
#define NLAYERS 5
#define NT 391                    // ceil(50000/128) row tiles of 128
#define SCAN_BLOCKS 196           // ceil(50000/256)

typedef unsigned long long ull;
typedef unsigned int u32;

// ----------------- persistent device scratch -----------------
__device__ float g_h[N_NODES * D];
__device__ float g_out[N_NODES * D];
__device__ float g_etab[9 * D];
__device__ float g_stats[2 * D];
__device__ float g_aff[2 * D];
__device__ int   g_deg[N_NODES];
__device__ int   g_off[N_NODES + 1];
__device__ int   g_cur[N_NODES];
__device__ int   g_csr[N_EDGES];
__device__ int   g_bsum[SCAN_BLOCKS];
__device__ int   g_boff[SCAN_BLOCKS + 1];
__device__ int   g_is64;
// hidden activations per tile: [row(128)][colpair(128)] ull = (hi_u32 | lo_u32<<32)
__device__ __align__(16) unsigned char g_hid[(size_t)NT * 131072];
// weight images: [n][k] bf16, hi plane then lo plane (65536B each)
__device__ __align__(16) unsigned char g_w1T[131072];   // n=256, k=128
__device__ __align__(16) unsigned char g_w2T[131072];   // n=128, k=256

// ----------------- helpers -----------------
__device__ __forceinline__ u32 smem_u32(const void* p) {
    u32 a;
    asm("{ .reg .u64 t; cvta.to.shared.u64 t, %1; cvt.u32.u64 %0, t; }" : "=r"(a) : "l"(p));
    return a;
}
__device__ __forceinline__ void gbar(int id) {   // 128-thread named barrier
    asm volatile("bar.sync %0, 128;" :: "r"(id) : "memory");
}
// split two floats into hi-pair / lo-pair bf16x2 words (x0 -> low half)
__device__ __forceinline__ void split2(float x0, float x1, u32& hp, u32& lp) {
    asm("cvt.rn.bf16x2.f32 %0, %1, %2;" : "=r"(hp) : "f"(x1), "f"(x0));
    float h0 = __uint_as_float(hp << 16);
    float h1 = __uint_as_float(hp & 0xffff0000u);
    float r0 = x0 - h0, r1 = x1 - h1;
    asm("cvt.rn.bf16x2.f32 %0, %1, %2;" : "=r"(lp) : "f"(r1), "f"(r0));
}
__device__ __forceinline__ void ldsm4(u32 addr, u32& r0, u32& r1, u32& r2, u32& r3) {
    asm volatile("ldmatrix.sync.aligned.m8n8.x4.shared.b16 {%0,%1,%2,%3}, [%4];"
                 : "=r"(r0), "=r"(r1), "=r"(r2), "=r"(r3) : "r"(addr));
}
__device__ __forceinline__ void mma16816(float* c, u32 a0, u32 a1, u32 a2, u32 a3,
                                         u32 b0, u32 b1) {
    asm volatile(
        "mma.sync.aligned.m16n8k16.row.col.f32.bf16.bf16.f32 "
        "{%0,%1,%2,%3}, {%4,%5,%6,%7}, {%8,%9}, {%0,%1,%2,%3};"
        : "+f"(c[0]), "+f"(c[1]), "+f"(c[2]), "+f"(c[3])
        : "r"(a0), "r"(a1), "r"(a2), "r"(a3), "r"(b0), "r"(b1));
}

__device__ __forceinline__ int getidx(const int* __restrict__ p, int i) {
    return g_is64 ? p[2 * i] : p[i];
}

// ----------------- merged setup: detect + etab + zero(deg,stats) ------------
__global__ void k_init(const int* __restrict__ x,
                       const float* __restrict__ bt,
                       const float* __restrict__ bd) {
    int i = blockIdx.x * blockDim.x + threadIdx.x;
    if (i < N_NODES) g_deg[i] = 0;
    if (blockIdx.x == 0 && threadIdx.x < 256) g_stats[threadIdx.x] = 0.f;
    if (blockIdx.x == 1 && threadIdx.x == 0) {
        int nz = 0;
        for (int j = 1; j < 128; j += 2) nz |= x[j];
        g_is64 = (nz == 0) ? 1 : 0;
    }
    if (blockIdx.x >= 2 && blockIdx.x < 11 && threadIdx.x < 128) {
        int code = blockIdx.x - 2, t = code / 3, d = code % 3, c = threadIdx.x;
        g_etab[code * D + c] = bt[t * D + c] + bd[d * D + c];
    }
}

__global__ void k_embed(const int* __restrict__ x,
                        const float* __restrict__ elem,
                        const float* __restrict__ chir) {
    int i = blockIdx.x * blockDim.x + threadIdx.x;
    if (i >= N_NODES * 32) return;
    int node = i >> 5, l = i & 31;
    int a = getidx(x, 2 * node);
    int c = getidx(x, 2 * node + 1);
    float4 va = __ldg((const float4*)(elem + a * D) + l);
    float4 vc = __ldg((const float4*)(chir + c * D) + l);
    ((float4*)(g_h + node * D))[l] =
        make_float4(va.x + vc.x, va.y + vc.y, va.z + vc.z, va.w + vc.w);
}

__global__ void k_hist(const int* __restrict__ ei) {
    int e = blockIdx.x * blockDim.x + threadIdx.x;
    if (e < N_EDGES) atomicAdd(&g_deg[getidx(ei, N_EDGES + e)], 1);
}

// ----------------- multi-block exclusive scan of g_deg -> g_off -------------
__global__ void k_scan1() {        // per-block reduce
    __shared__ int sh[256];
    int tid = threadIdx.x;
    int i = blockIdx.x * 256 + tid;
    int v = (i < N_NODES) ? g_deg[i] : 0;
    sh[tid] = v;
    __syncthreads();
    for (int off = 128; off > 0; off >>= 1) {
        if (tid < off) sh[tid] += sh[tid + off];
        __syncthreads();
    }
    if (tid == 0) g_bsum[blockIdx.x] = sh[0];
}

__global__ void k_scan2() {        // single-block scan of SCAN_BLOCKS sums
    __shared__ int sh[256];
    int tid = threadIdx.x;
    int v = (tid < SCAN_BLOCKS) ? g_bsum[tid] : 0;
    sh[tid] = v;
    __syncthreads();
    for (int off = 1; off < 256; off <<= 1) {
        int t = (tid >= off) ? sh[tid - off] : 0;
        __syncthreads();
        sh[tid] += t;
        __syncthreads();
    }
    if (tid < SCAN_BLOCKS) g_boff[tid] = sh[tid] - v;   // exclusive
    if (tid == SCAN_BLOCKS - 1) g_boff[SCAN_BLOCKS] = sh[tid];
}

__global__ void k_scan3() {        // local scan + block offset
    __shared__ int sh[256];
    int tid = threadIdx.x;
    int i = blockIdx.x * 256 + tid;
    int v = (i < N_NODES) ? g_deg[i] : 0;
    sh[tid] = v;
    __syncthreads();
    for (int off = 1; off < 256; off <<= 1) {
        int t = (tid >= off) ? sh[tid - off] : 0;
        __syncthreads();
        sh[tid] += t;
        __syncthreads();
    }
    int base = g_boff[blockIdx.x];
    if (i < N_NODES) {
        int ex = base + sh[tid] - v;
        g_off[i] = ex;
        g_cur[i] = ex;
    }
    if (i == N_NODES - 1 || (blockIdx.x == SCAN_BLOCKS - 1 && tid == 255))
        g_off[N_NODES] = g_boff[SCAN_BLOCKS];
}

__global__ void k_fill(const int* __restrict__ ei, const int* __restrict__ ea) {
    int e = blockIdx.x * blockDim.x + threadIdx.x;
    if (e < N_EDGES) {
        int src = getidx(ei, e);
        int dst = getidx(ei, N_EDGES + e);
        int t = getidx(ea, 2 * e);
        int d = getidx(ea, 2 * e + 1);
        int pos = atomicAdd(&g_cur[dst], 1);
        g_csr[pos] = src | ((t * 3 + d) << 20);
    }
}

// weight images: B[n][k] = W[k][n], split bf16 hi/lo planes
__global__ void k_prep(const float* __restrict__ W1, const float* __restrict__ W2) {
    int idx = blockIdx.x * blockDim.x + threadIdx.x;
    if (idx < 16384) {                        // W1: n 0..255, k pairs 0..63
        int n = idx >> 6, kp = idx & 63, k = kp * 2;
        float a = __ldg(W1 + k * 256 + n);
        float b = __ldg(W1 + (k + 1) * 256 + n);
        u32 hp, lp; split2(a, b, hp, lp);
        ((u32*)g_w1T)[n * 64 + kp] = hp;
        ((u32*)g_w1T)[16384 + n * 64 + kp] = lp;
    } else if (idx < 32768) {                 // W2: n 0..127, k pairs 0..127
        int q = idx - 16384;
        int n = q >> 7, kp = q & 127, k = kp * 2;
        float a = __ldg(W2 + k * 128 + n);
        float b = __ldg(W2 + (k + 1) * 128 + n);
        u32 hp, lp; split2(a, b, hp, lp);
        ((u32*)g_w2T)[n * 128 + kp] = hp;
        ((u32*)g_w2T)[16384 + n * 128 + kp] = lp;
    }
}

// ----------------- fused agg + GEMM1 ----------------------------------------
// smem: B hi/lo [256][272B], A hi/lo [128][272B], bias[256], etab[9*128]
#define KA_B_HI 0
#define KA_B_LO 69632
#define KA_A_HI 139264
#define KA_A_LO 174080
#define KA_BIAS 208896
#define KA_ETAB 209920
#define KA_SMEM 214528

__device__ __forceinline__ void agg_one(float4& acc, float4 hv, const float* et,
                                        int code, int c0, int mode,
                                        float4 sc, float4 sf) {
    if (mode) {
        hv.x = fmaxf(fmaf(hv.x, sc.x, sf.x), 0.f);
        hv.y = fmaxf(fmaf(hv.y, sc.y, sf.y), 0.f);
        hv.z = fmaxf(fmaf(hv.z, sc.z, sf.z), 0.f);
        hv.w = fmaxf(fmaf(hv.w, sc.w, sf.w), 0.f);
    }
    float4 ev = *(const float4*)(et + code * D + c0);
    acc.x += fmaxf(hv.x + ev.x, 0.f);
    acc.y += fmaxf(hv.y + ev.y, 0.f);
    acc.z += fmaxf(hv.z + ev.z, 0.f);
    acc.w += fmaxf(hv.w + ev.w, 0.f);
}

__global__ void __launch_bounds__(512, 1) kA(const float* __restrict__ b1, int layer) {
    extern __shared__ char sm[];
    u32 sb = smem_u32(sm);
    const int tid = threadIdx.x;
    const int warp = tid >> 5, lane = tid & 31;

    // stage weights + bias + etab (once)
    {
        const uint4* src = (const uint4*)g_w1T;
        for (int i = tid; i < 8192; i += 512) {
            int p = i >> 12, r = (i >> 4) & 255, w = i & 15;
            *(uint4*)(sm + KA_B_HI + p * 69632 + r * 272 + w * 16) =
                src[p * 4096 + r * 16 + w];
        }
        if (tid < 256) ((float*)(sm + KA_BIAS))[tid] = __ldg(b1 + tid);
        for (int i = tid; i < 9 * D; i += 512)
            ((float*)(sm + KA_ETAB))[i] = g_etab[i];
    }
    __syncthreads();

    const int mode = (layer > 0);
    const float* __restrict__ in = mode ? g_out : g_h;
    const float* et = (const float*)(sm + KA_ETAB);
    const int c0 = lane * 4;

    float4 sc = make_float4(1.f, 1.f, 1.f, 1.f);
    float4 sf = make_float4(0.f, 0.f, 0.f, 0.f);
    if (mode) {
        sc = *(const float4*)&g_aff[c0];
        sf = *(const float4*)&g_aff[D + c0];
    }

    const int wr = warp >> 2, wc = warp & 3;        // 4 x 4 warp grid, 32x64 tiles
    const int bar = wr + 1;                          // group-local named barrier
    const u32 aHi = sb + KA_A_HI + (wr * 32 + (lane & 15)) * 272 + (lane >> 4) * 16;
    const u32 aLo = aHi + (KA_A_LO - KA_A_HI);
    const u32 bHi = sb + KA_B_HI + (wc * 64 + (lane & 15)) * 272 + (lane >> 4) * 16;
    const u32 bLo = bHi + 69632;
    const float* bias = (const float*)(sm + KA_BIAS);

    for (int tile = blockIdx.x; tile < NT; tile += gridDim.x) {
        // fused aggregation: each warp aggregates its group's 8 rows into smem A
#pragma unroll 1
        for (int r8 = 0; r8 < 8; r8++) {
            int r = warp * 8 + r8;
            int node = tile * 128 + r;
            float4 acc = make_float4(0.f, 0.f, 0.f, 0.f);
            if (node < N_NODES) {
                int beg = g_off[node], end = g_off[node + 1];
                int e = beg;
                for (; e + 4 <= end; e += 4) {
                    int v0 = __ldg(g_csr + e);
                    int v1 = __ldg(g_csr + e + 1);
                    int v2 = __ldg(g_csr + e + 2);
                    int v3 = __ldg(g_csr + e + 3);
                    float4 h0 = __ldg((const float4*)(in + (size_t)(v0 & 0xFFFFF) * D) + lane);
                    float4 h1 = __ldg((const float4*)(in + (size_t)(v1 & 0xFFFFF) * D) + lane);
                    float4 h2 = __ldg((const float4*)(in + (size_t)(v2 & 0xFFFFF) * D) + lane);
                    float4 h3 = __ldg((const float4*)(in + (size_t)(v3 & 0xFFFFF) * D) + lane);
                    agg_one(acc, h0, et, v0 >> 20, c0, mode, sc, sf);
                    agg_one(acc, h1, et, v1 >> 20, c0, mode, sc, sf);
                    agg_one(acc, h2, et, v2 >> 20, c0, mode, sc, sf);
                    agg_one(acc, h3, et, v3 >> 20, c0, mode, sc, sf);
                }
                for (; e < end; e++) {
                    int v = __ldg(g_csr + e);
                    float4 hv = __ldg((const float4*)(in + (size_t)(v & 0xFFFFF) * D) + lane);
                    agg_one(acc, hv, et, v >> 20, c0, mode, sc, sf);
                }
                float4 hd = __ldg((const float4*)(in + (size_t)node * D) + lane);
                if (mode) {
                    hd.x = fmaxf(fmaf(hd.x, sc.x, sf.x), 0.f);
                    hd.y = fmaxf(fmaf(hd.y, sc.y, sf.y), 0.f);
                    hd.z = fmaxf(fmaf(hd.z, sc.z, sf.z), 0.f);
                    hd.w = fmaxf(fmaf(hd.w, sc.w, sf.w), 0.f);
                }
                acc.x += hd.x; acc.y += hd.y; acc.z += hd.z; acc.w += hd.w;
            }
            u32 h0, l0, h1, l1;
            split2(acc.x, acc.y, h0, l0);
            split2(acc.z, acc.w, h1, l1);
            *(ull*)(sm + KA_A_HI + r * 272 + lane * 8) = (ull)h0 | ((ull)h1 << 32);
            *(ull*)(sm + KA_A_LO + r * 272 + lane * 8) = (ull)l0 | ((ull)l1 << 32);
        }
        gbar(bar);   // group's A rows ready (producers == consumers == this group)

        float acc[2][8][4];
#pragma unroll
        for (int a = 0; a < 2; a++)
#pragma unroll
            for (int b = 0; b < 8; b++)
#pragma unroll
                for (int c = 0; c < 4; c++) acc[a][b][c] = 0.f;

        for (int ks = 0; ks < 8; ks++) {
            const u32 ko = ks * 32;
            u32 ah[2][4], al[2][4];
#pragma unroll
            for (int mt = 0; mt < 2; mt++) {
                ldsm4(aHi + mt * (16 * 272) + ko, ah[mt][0], ah[mt][1], ah[mt][2], ah[mt][3]);
                ldsm4(aLo + mt * (16 * 272) + ko, al[mt][0], al[mt][1], al[mt][2], al[mt][3]);
            }
#pragma unroll
            for (int g = 0; g < 4; g++) {
                u32 bh0, bh1, bh2, bh3, bl0, bl1, bl2, bl3;
                ldsm4(bHi + g * (16 * 272) + ko, bh0, bh1, bh2, bh3);
                ldsm4(bLo + g * (16 * 272) + ko, bl0, bl1, bl2, bl3);
#pragma unroll
                for (int mt = 0; mt < 2; mt++) {
                    mma16816(acc[mt][2 * g],     ah[mt][0], ah[mt][1], ah[mt][2], ah[mt][3], bh0, bh2);
                    mma16816(acc[mt][2 * g + 1], ah[mt][0], ah[mt][1], ah[mt][2], ah[mt][3], bh1, bh3);
                    mma16816(acc[mt][2 * g],     ah[mt][0], ah[mt][1], ah[mt][2], ah[mt][3], bl0, bl2);
                    mma16816(acc[mt][2 * g + 1], ah[mt][0], ah[mt][1], ah[mt][2], ah[mt][3], bl1, bl3);
                    mma16816(acc[mt][2 * g],     al[mt][0], al[mt][1], al[mt][2], al[mt][3], bh0, bh2);
                    mma16816(acc[mt][2 * g + 1], al[mt][0], al[mt][1], al[mt][2], al[mt][3], bh1, bh3);
                }
            }
        }

        // epilogue: bias + relu + re-split -> interleaved (hi,lo) ull stores
        ull* hid64 = (ull*)(g_hid + (size_t)tile * 131072);
        const int m0 = wr * 32, n0 = wc * 64;
#pragma unroll
        for (int mt = 0; mt < 2; mt++)
#pragma unroll
            for (int nt = 0; nt < 8; nt++) {
                int col = n0 + nt * 8 + 2 * (lane & 3);
                int r0 = m0 + mt * 16 + (lane >> 2);
                float bv0 = bias[col], bv1 = bias[col + 1];
                u32 hp, lp;
                float v0 = fmaxf(acc[mt][nt][0] + bv0, 0.f);
                float v1 = fmaxf(acc[mt][nt][1] + bv1, 0.f);
                split2(v0, v1, hp, lp);
                hid64[r0 * 128 + (col >> 1)] = (ull)hp | ((ull)lp << 32);
                v0 = fmaxf(acc[mt][nt][2] + bv0, 0.f);
                v1 = fmaxf(acc[mt][nt][3] + bv1, 0.f);
                split2(v0, v1, hp, lp);
                hid64[(r0 + 8) * 128 + (col >> 1)] = (ull)hp | ((ull)lp << 32);
            }
        gbar(bar);   // group done reading A -> safe to overwrite next tile
    }
}

// ----------------- GEMM2: g_out = hidden @ W2 + b2, fused BN stats ----------
// smem: B hi/lo [128][528B], A hi/lo [128][272B] (half-K staged), bias[128]
#define KB_B_HI 0
#define KB_B_LO 67584
#define KB_A_HI 135168
#define KB_A_LO 169984
#define KB_BIAS 204800
#define KB_SMEM 205312

__global__ void __launch_bounds__(512, 1) kB(const float* __restrict__ b2) {
    extern __shared__ char sm[];
    u32 sb = smem_u32(sm);
    const int tid = threadIdx.x;
    const int warp = tid >> 5, lane = tid & 31;

    {
        const uint4* src = (const uint4*)g_w2T;
        for (int i = tid; i < 8192; i += 512) {
            int p = i >> 12, r = (i >> 5) & 127, w = i & 31;
            *(uint4*)(sm + KB_B_HI + p * 67584 + r * 528 + w * 16) =
                src[p * 4096 + r * 32 + w];
        }
        if (tid < 128) ((float*)(sm + KB_BIAS))[tid] = __ldg(b2 + tid);
    }
    __syncthreads();

    const int wr = warp >> 2, wc = warp & 3;        // 4 x 4 grid, 32x32 tiles
    const int bar = wr + 1;
    const int gt = tid & 127;                        // thread index within group
    const int R0 = wr * 32;                          // group's A-row base
    const u32 aHi = sb + KB_A_HI + (wr * 32 + (lane & 15)) * 272 + (lane >> 4) * 16;
    const u32 aLo = aHi + (KB_A_LO - KB_A_HI);
    const u32 bHi = sb + KB_B_HI + (wc * 32 + (lane & 15)) * 528 + (lane >> 4) * 16;
    const u32 bLo = bHi + 67584;
    const float* bias = (const float*)(sm + KB_BIAS);

    // BN stat accumulators: this thread's columns are fixed across tiles
    float st_s[4][2], st_s2[4][2];
#pragma unroll
    for (int nt = 0; nt < 4; nt++) {
        st_s[nt][0] = st_s[nt][1] = 0.f;
        st_s2[nt][0] = st_s2[nt][1] = 0.f;
    }

    for (int tile = blockIdx.x; tile < NT; tile += gridDim.x) {
        float acc[2][4][4];
#pragma unroll
        for (int a = 0; a < 2; a++)
#pragma unroll
            for (int b = 0; b < 4; b++)
#pragma unroll
                for (int c = 0; c < 4; c++) acc[a][b][c] = 0.f;

        const ull* hid64 = (const ull*)(g_hid + (size_t)tile * 131072);
        for (int pass = 0; pass < 2; pass++) {
            // stage group's own 32 A rows: de-interleave (hi,lo) -> planes
            for (int i = gt; i < 2048; i += 128) {
                int r = R0 + (i >> 6), cp = i & 63;
                ull v = __ldg(hid64 + r * 128 + pass * 64 + cp);
                *(u32*)(sm + KB_A_HI + r * 272 + cp * 4) = (u32)v;
                *(u32*)(sm + KB_A_LO + r * 272 + cp * 4) = (u32)(v >> 32);
            }
            gbar(bar);   // group's rows staged (producers == consumers)

            for (int ks = 0; ks < 8; ks++) {
                const u32 ko = ks * 32;
                const u32 bo = pass * 256 + ko;
                u32 ah[2][4], al[2][4];
#pragma unroll
                for (int mt = 0; mt < 2; mt++) {
                    ldsm4(aHi + mt * (16 * 272) + ko, ah[mt][0], ah[mt][1], ah[mt][2], ah[mt][3]);
                    ldsm4(aLo + mt * (16 * 272) + ko, al[mt][0], al[mt][1], al[mt][2], al[mt][3]);
                }
#pragma unroll
                for (int g = 0; g < 2; g++) {
                    u32 bh0, bh1, bh2, bh3, bl0, bl1, bl2, bl3;
                    ldsm4(bHi + g * (16 * 528) + bo, bh0, bh1, bh2, bh3);
                    ldsm4(bLo + g * (16 * 528) + bo, bl0, bl1, bl2, bl3);
#pragma unroll
                    for (int mt = 0; mt < 2; mt++) {
                        mma16816(acc[mt][2 * g],     ah[mt][0], ah[mt][1], ah[mt][2], ah[mt][3], bh0, bh2);
                        mma16816(acc[mt][2 * g + 1], ah[mt][0], ah[mt][1], ah[mt][2], ah[mt][3], bh1, bh3);
                        mma16816(acc[mt][2 * g],     ah[mt][0], ah[mt][1], ah[mt][2], ah[mt][3], bl0, bl2);
                        mma16816(acc[mt][2 * g + 1], ah[mt][0], ah[mt][1], ah[mt][2], ah[mt][3], bl1, bl3);
                        mma16816(acc[mt][2 * g],     al[mt][0], al[mt][1], al[mt][2], al[mt][3], bh0, bh2);
                        mma16816(acc[mt][2 * g + 1], al[mt][0], al[mt][1], al[mt][2], al[mt][3], bh1, bh3);
                    }
                }
            }
            gbar(bar);   // group done reading A -> safe to restage
        }

        // epilogue: bias, write fp32 g_out, accumulate BN stats in registers
        const int m0 = wr * 32, n0 = wc * 32;
#pragma unroll
        for (int mt = 0; mt < 2; mt++)
#pragma unroll
            for (int nt = 0; nt < 4; nt++) {
                int col = n0 + nt * 8 + 2 * (lane & 3);
                int r0 = tile * 128 + m0 + mt * 16 + (lane >> 2);
                float bv0 = bias[col], bv1 = bias[col + 1];
                if (r0 < N_NODES) {
                    float o0 = acc[mt][nt][0] + bv0;
                    float o1 = acc[mt][nt][1] + bv1;
                    *(float2*)(g_out + (size_t)r0 * D + col) = make_float2(o0, o1);
                    st_s[nt][0] += o0;  st_s2[nt][0] += o0 * o0;
                    st_s[nt][1] += o1;  st_s2[nt][1] += o1 * o1;
                }
                if (r0 + 8 < N_NODES) {
                    float o0 = acc[mt][nt][2] + bv0;
                    float o1 = acc[mt][nt][3] + bv1;
                    *(float2*)(g_out + (size_t)(r0 + 8) * D + col) = make_float2(o0, o1);
                    st_s[nt][0] += o0;  st_s2[nt][0] += o0 * o0;
                    st_s[nt][1] += o1;  st_s2[nt][1] += o1 * o1;
                }
            }
    }

    // reduce stats across the 8 lane-groups sharing columns (lane stride 4)
#pragma unroll
    for (int nt = 0; nt < 4; nt++)
#pragma unroll
        for (int p = 0; p < 2; p++) {
#pragma unroll
            for (int off = 16; off >= 4; off >>= 1) {
                st_s[nt][p]  += __shfl_xor_sync(0xffffffffu, st_s[nt][p],  off);
                st_s2[nt][p] += __shfl_xor_sync(0xffffffffu, st_s2[nt][p], off);
            }
        }
    if (lane < 4) {
        const int n0 = wc * 32;
#pragma unroll
        for (int nt = 0; nt < 4; nt++) {
            int col = n0 + nt * 8 + 2 * lane;
            atomicAdd(&g_stats[col],           st_s[nt][0]);
            atomicAdd(&g_stats[col + 1],       st_s[nt][1]);
            atomicAdd(&g_stats[128 + col],     st_s2[nt][0]);
            atomicAdd(&g_stats[128 + col + 1], st_s2[nt][1]);
        }
    }
}

// ----------------- BN fold: stats -> per-feature scale/shift, self-reset ----
__global__ void k_bnfold(const float* __restrict__ gamma, const float* __restrict__ beta) {
    int c = threadIdx.x;
    if (c < D) {
        float sum = g_stats[c], sum2 = g_stats[128 + c];
        const float invN = 1.0f / (float)N_NODES;
        float mean = sum * invN;
        float var = sum2 * invN - mean * mean;
        float scl = rsqrtf(var + 1e-5f) * __ldg(gamma + c);
        g_aff[c] = scl;
        g_aff[128 + c] = __ldg(beta + c) - mean * scl;
        g_stats[c] = 0.f;
        g_stats[128 + c] = 0.f;
    }
}

// ----------------- final: apply last BN (no relu) -> d_out ------------------
__global__ void k_final(float* __restrict__ out) {
    int i = blockIdx.x * blockDim.x + threadIdx.x;
    if (i >= N_NODES * 32) return;
    int c0 = (i & 31) * 4;
    float4 v = ((const float4*)g_out)[i];
    float4 sc = *(const float4*)&g_aff[c0];
    float4 sf = *(const float4*)&g_aff[D + c0];
    v.x = fmaf(v.x, sc.x, sf.x);
    v.y = fmaf(v.y, sc.y, sf.y);
    v.z = fmaf(v.z, sc.z, sf.z);
    v.w = fmaf(v.w, sc.w, sf.w);
    ((float4*)out)[i] = v;
}

// ----------------- launch -----------------
extern "C" void kernel_launch(void* const* d_in, const int* in_sizes, int n_in,
                              void* d_out, int out_size) {
    const int*   x    = (const int*)d_in[0];
    const int*   ei   = (const int*)d_in[1];
    const int*   ea   = (const int*)d_in[2];
    const float* elem = (const float*)d_in[3];
    const float* chir = (const float*)d_in[4];
    const float* bt   = (const float*)d_in[5];
    const float* bd   = (const float*)d_in[6];
    const float* W1   = (const float*)d_in[7];
    const float* b1   = (const float*)d_in[8];
    const float* W2   = (const float*)d_in[9];
    const float* b2   = (const float*)d_in[10];
    const float* bng  = (const float*)d_in[11];
    const float* bnb  = (const float*)d_in[12];
    float* out = (float*)d_out;

    static int attr_done = 0;
    if (!attr_done) {
        cudaFuncSetAttribute(kA, cudaFuncAttributeMaxDynamicSharedMemorySize, KA_SMEM);
        cudaFuncSetAttribute(kB, cudaFuncAttributeMaxDynamicSharedMemorySize, KB_SMEM);
        attr_done = 1;
    }

    k_init<<<(N_NODES + 255) / 256, 256>>>(x, bt, bd);
    k_embed<<<(N_NODES * 32 + 255) / 256, 256>>>(x, elem, chir);
    k_hist<<<(N_EDGES + 255) / 256, 256>>>(ei);
    k_scan1<<<SCAN_BLOCKS, 256>>>();
    k_scan2<<<1, 256>>>();
    k_scan3<<<SCAN_BLOCKS, 256>>>();
    k_fill<<<(N_EDGES + 255) / 256, 256>>>(ei, ea);
    k_prep<<<128, 256>>>(W1, W2);

    for (int l = 0; l < NLAYERS; l++) {
        kA<<<148, 512, KA_SMEM>>>(b1, l);
        kB<<<148, 512, KB_SMEM>>>(b2);
        k_bnfold<<<1, 128>>>(bng + l * D, bnb + l * D);
    }
    k_final<<<(N_NODES * 32 + 255) / 256, 256>>>(out);
}

// round 15
// speedup vs baseline: 1.4968x; 1.0515x over previous
#include <cuda_runtime.h>

#define N_NODES 50000
#define N_EDGES 600000
#define D 128
#define NLAYERS 5
#define NT 391                    // ceil(50000/128) row tiles of 128
#define OFF_BLOCKS 196            // ceil(50000/256)

typedef unsigned long long ull;
typedef unsigned int u32;

// ----------------- persistent device scratch -----------------
__device__ float g_h[N_NODES * D];
__device__ float g_out[N_NODES * D];
__device__ float g_etab[9 * D];
__device__ float g_stats[2 * 256];     // double-buffered by layer parity
__device__ float g_aff[2 * D];
__device__ int   g_deg[N_NODES];
__device__ int   g_off[N_NODES];
__device__ int   g_cur[N_NODES];
__device__ int   g_csr[N_EDGES];
__device__ int   g_total;
__device__ int   g_is64;
// hidden activations per tile: [row(128)][colpair(128)] ull = (hi_u32 | lo_u32<<32)
__device__ __align__(16) unsigned char g_hid[(size_t)NT * 131072];
// weight images: [n][k] bf16, hi plane then lo plane (65536B each)
__device__ __align__(16) unsigned char g_w1T[131072];   // n=256, k=128
__device__ __align__(16) unsigned char g_w2T[131072];   // n=128, k=256

// ----------------- helpers -----------------
__device__ __forceinline__ u32 smem_u32(const void* p) {
    u32 a;
    asm("{ .reg .u64 t; cvta.to.shared.u64 t, %1; cvt.u32.u64 %0, t; }" : "=r"(a) : "l"(p));
    return a;
}
__device__ __forceinline__ void gbar(int id) {   // 128-thread named barrier
    asm volatile("bar.sync %0, 128;" :: "r"(id) : "memory");
}
// split two floats into hi-pair / lo-pair bf16x2 words (x0 -> low half)
__device__ __forceinline__ void split2(float x0, float x1, u32& hp, u32& lp) {
    asm("cvt.rn.bf16x2.f32 %0, %1, %2;" : "=r"(hp) : "f"(x1), "f"(x0));
    float h0 = __uint_as_float(hp << 16);
    float h1 = __uint_as_float(hp & 0xffff0000u);
    float r0 = x0 - h0, r1 = x1 - h1;
    asm("cvt.rn.bf16x2.f32 %0, %1, %2;" : "=r"(lp) : "f"(r1), "f"(r0));
}
__device__ __forceinline__ void ldsm4(u32 addr, u32& r0, u32& r1, u32& r2, u32& r3) {
    asm volatile("ldmatrix.sync.aligned.m8n8.x4.shared.b16 {%0,%1,%2,%3}, [%4];"
                 : "=r"(r0), "=r"(r1), "=r"(r2), "=r"(r3) : "r"(addr));
}
__device__ __forceinline__ void mma16816(float* c, u32 a0, u32 a1, u32 a2, u32 a3,
                                         u32 b0, u32 b1) {
    asm volatile(
        "mma.sync.aligned.m16n8k16.row.col.f32.bf16.bf16.f32 "
        "{%0,%1,%2,%3}, {%4,%5,%6,%7}, {%8,%9}, {%0,%1,%2,%3};"
        : "+f"(c[0]), "+f"(c[1]), "+f"(c[2]), "+f"(c[3])
        : "r"(a0), "r"(a1), "r"(a2), "r"(a3), "r"(b0), "r"(b1));
}

__device__ __forceinline__ int getidx(const int* __restrict__ p, int i) {
    return g_is64 ? p[2 * i] : p[i];
}

// ----------------- setup 1: zero(deg,stats,total) + detect + etab ------------
__global__ void k_init(const int* __restrict__ x,
                       const float* __restrict__ bt,
                       const float* __restrict__ bd) {
    int i = blockIdx.x * blockDim.x + threadIdx.x;
    if (i < N_NODES) g_deg[i] = 0;
    if (i < 512) g_stats[i] = 0.f;
    if (i == 0) g_total = 0;
    if (blockIdx.x == 12 && threadIdx.x == 0) {
        int nz = 0;
        for (int j = 1; j < 128; j += 2) nz |= x[j];
        g_is64 = (nz == 0) ? 1 : 0;
    }
    if (blockIdx.x >= 2 && blockIdx.x < 11 && threadIdx.x < 128) {
        int code = blockIdx.x - 2, t = code / 3, d = code % 3, c = threadIdx.x;
        g_etab[code * D + c] = bt[t * D + c] + bd[d * D + c];
    }
}

// ----------------- setup 2: embed + hist + weight prep (merged) --------------
__global__ void k_setup(const int* __restrict__ x,
                        const float* __restrict__ elem,
                        const float* __restrict__ chir,
                        const int* __restrict__ ei,
                        const float* __restrict__ W1,
                        const float* __restrict__ W2) {
    int i = blockIdx.x * blockDim.x + threadIdx.x;
    // embed: 50000*32 slots
    if (i < N_NODES * 32) {
        int node = i >> 5, l = i & 31;
        int a = getidx(x, 2 * node);
        int c = getidx(x, 2 * node + 1);
        float4 va = __ldg((const float4*)(elem + a * D) + l);
        float4 vc = __ldg((const float4*)(chir + c * D) + l);
        ((float4*)(g_h + node * D))[l] =
            make_float4(va.x + vc.x, va.y + vc.y, va.z + vc.z, va.w + vc.w);
    }
    // hist
    if (i < N_EDGES) atomicAdd(&g_deg[getidx(ei, N_EDGES + i)], 1);
    // weight prep
    if (i < 16384) {                          // W1: n 0..255, k pairs 0..63
        int n = i >> 6, kp = i & 63, k = kp * 2;
        float a = __ldg(W1 + k * 256 + n);
        float b = __ldg(W1 + (k + 1) * 256 + n);
        u32 hp, lp; split2(a, b, hp, lp);
        ((u32*)g_w1T)[n * 64 + kp] = hp;
        ((u32*)g_w1T)[16384 + n * 64 + kp] = lp;
    } else if (i < 32768) {                   // W2: n 0..127, k pairs 0..127
        int q = i - 16384;
        int n = q >> 7, kp = q & 127, k = kp * 2;
        float a = __ldg(W2 + k * 128 + n);
        float b = __ldg(W2 + (k + 1) * 128 + n);
        u32 hp, lp; split2(a, b, hp, lp);
        ((u32*)g_w2T)[n * 128 + kp] = hp;
        ((u32*)g_w2T)[16384 + n * 128 + kp] = lp;
    }
}

// ----------------- offsets: block-local scan + atomic base -------------------
__global__ void k_offsets() {
    __shared__ int sh[256];
    __shared__ int base_s;
    int tid = threadIdx.x;
    int i = blockIdx.x * 256 + tid;
    int v = (i < N_NODES) ? g_deg[i] : 0;
    sh[tid] = v;
    __syncthreads();
    for (int off = 1; off < 256; off <<= 1) {
        int t = (tid >= off) ? sh[tid - off] : 0;
        __syncthreads();
        sh[tid] += t;
        __syncthreads();
    }
    if (tid == 255) base_s = atomicAdd(&g_total, sh[255]);
    __syncthreads();
    if (i < N_NODES) {
        int ex = base_s + sh[tid] - v;
        g_off[i] = ex;
        g_cur[i] = ex;
    }
}

__global__ void k_fill(const int* __restrict__ ei, const int* __restrict__ ea) {
    int e = blockIdx.x * blockDim.x + threadIdx.x;
    if (e < N_EDGES) {
        int src = getidx(ei, e);
        int dst = getidx(ei, N_EDGES + e);
        int t = getidx(ea, 2 * e);
        int d = getidx(ea, 2 * e + 1);
        int pos = atomicAdd(&g_cur[dst], 1);
        g_csr[pos] = src | ((t * 3 + d) << 20);
    }
}

// ----------------- fused agg + GEMM1 (+ in-kernel BN fold) -------------------
// smem: B hi/lo [256][272B], A hi/lo [128][272B], bias[256], etab[9*128], aff[256]
#define KA_B_HI 0
#define KA_B_LO 69632
#define KA_A_HI 139264
#define KA_A_LO 174080
#define KA_BIAS 208896
#define KA_ETAB 209920
#define KA_AFF  214528
#define KA_SMEM 215552

__device__ __forceinline__ void agg_one(float4& acc, float4 hv, const float* et,
                                        int code, int c0, int mode,
                                        float4 sc, float4 sf) {
    if (mode) {
        hv.x = fmaxf(fmaf(hv.x, sc.x, sf.x), 0.f);
        hv.y = fmaxf(fmaf(hv.y, sc.y, sf.y), 0.f);
        hv.z = fmaxf(fmaf(hv.z, sc.z, sf.z), 0.f);
        hv.w = fmaxf(fmaf(hv.w, sc.w, sf.w), 0.f);
    }
    float4 ev = *(const float4*)(et + code * D + c0);
    acc.x += fmaxf(hv.x + ev.x, 0.f);
    acc.y += fmaxf(hv.y + ev.y, 0.f);
    acc.z += fmaxf(hv.z + ev.z, 0.f);
    acc.w += fmaxf(hv.w + ev.w, 0.f);
}

__global__ void __launch_bounds__(512, 1) kA(const float* __restrict__ b1, int layer,
                                             const float* __restrict__ gamma,
                                             const float* __restrict__ beta) {
    extern __shared__ char sm[];
    u32 sb = smem_u32(sm);
    const int tid = threadIdx.x;
    const int warp = tid >> 5, lane = tid & 31;
    const int mode = (layer > 0);

    // stage weights + bias + etab + fold BN affine (once)
    {
        const uint4* src = (const uint4*)g_w1T;
        for (int i = tid; i < 8192; i += 512) {
            int p = i >> 12, r = (i >> 4) & 255, w = i & 15;
            *(uint4*)(sm + KA_B_HI + p * 69632 + r * 272 + w * 16) =
                src[p * 4096 + r * 16 + w];
        }
        if (tid < 256) ((float*)(sm + KA_BIAS))[tid] = __ldg(b1 + tid);
        for (int i = tid; i < 9 * D; i += 512)
            ((float*)(sm + KA_ETAB))[i] = g_etab[i];
        if (mode && tid < 128) {
            const float* st = g_stats + (((layer - 1) & 1) << 8);
            float sum = st[tid], sum2 = st[128 + tid];
            const float invN = 1.0f / (float)N_NODES;
            float mean = sum * invN;
            float var = sum2 * invN - mean * mean;
            float scl = rsqrtf(var + 1e-5f) * __ldg(gamma + tid);
            ((float*)(sm + KA_AFF))[tid] = scl;
            ((float*)(sm + KA_AFF))[128 + tid] = __ldg(beta + tid) - mean * scl;
        }
        // zero this layer's stats buffer (benign same-value race across CTAs;
        // kB(layer) starts only after all kA CTAs retire)
        if (tid < 256) g_stats[((layer & 1) << 8) + tid] = 0.f;
    }
    __syncthreads();

    const float* __restrict__ in = mode ? g_out : g_h;
    const float* et = (const float*)(sm + KA_ETAB);
    const int c0 = lane * 4;

    float4 sc = make_float4(1.f, 1.f, 1.f, 1.f);
    float4 sf = make_float4(0.f, 0.f, 0.f, 0.f);
    if (mode) {
        sc = *(const float4*)((const float*)(sm + KA_AFF) + c0);
        sf = *(const float4*)((const float*)(sm + KA_AFF) + D + c0);
    }

    const int wr = warp >> 2, wc = warp & 3;        // 4 x 4 warp grid, 32x64 tiles
    const int bar = wr + 1;                          // group-local named barrier
    const u32 aHi = sb + KA_A_HI + (wr * 32 + (lane & 15)) * 272 + (lane >> 4) * 16;
    const u32 aLo = aHi + (KA_A_LO - KA_A_HI);
    const u32 bHi = sb + KA_B_HI + (wc * 64 + (lane & 15)) * 272 + (lane >> 4) * 16;
    const u32 bLo = bHi + 69632;
    const float* bias = (const float*)(sm + KA_BIAS);

    for (int tile = blockIdx.x; tile < NT; tile += gridDim.x) {
        // fused aggregation: each warp aggregates its group's 8 rows into smem A
#pragma unroll 1
        for (int r8 = 0; r8 < 8; r8++) {
            int r = warp * 8 + r8;
            int node = tile * 128 + r;
            float4 acc = make_float4(0.f, 0.f, 0.f, 0.f);
            if (node < N_NODES) {
                int beg = g_off[node];
                int end = beg + g_deg[node];
                int e = beg;
                for (; e + 4 <= end; e += 4) {
                    int v0 = __ldg(g_csr + e);
                    int v1 = __ldg(g_csr + e + 1);
                    int v2 = __ldg(g_csr + e + 2);
                    int v3 = __ldg(g_csr + e + 3);
                    float4 h0 = __ldg((const float4*)(in + (size_t)(v0 & 0xFFFFF) * D) + lane);
                    float4 h1 = __ldg((const float4*)(in + (size_t)(v1 & 0xFFFFF) * D) + lane);
                    float4 h2 = __ldg((const float4*)(in + (size_t)(v2 & 0xFFFFF) * D) + lane);
                    float4 h3 = __ldg((const float4*)(in + (size_t)(v3 & 0xFFFFF) * D) + lane);
                    agg_one(acc, h0, et, v0 >> 20, c0, mode, sc, sf);
                    agg_one(acc, h1, et, v1 >> 20, c0, mode, sc, sf);
                    agg_one(acc, h2, et, v2 >> 20, c0, mode, sc, sf);
                    agg_one(acc, h3, et, v3 >> 20, c0, mode, sc, sf);
                }
                for (; e < end; e++) {
                    int v = __ldg(g_csr + e);
                    float4 hv = __ldg((const float4*)(in + (size_t)(v & 0xFFFFF) * D) + lane);
                    agg_one(acc, hv, et, v >> 20, c0, mode, sc, sf);
                }
                float4 hd = __ldg((const float4*)(in + (size_t)node * D) + lane);
                if (mode) {
                    hd.x = fmaxf(fmaf(hd.x, sc.x, sf.x), 0.f);
                    hd.y = fmaxf(fmaf(hd.y, sc.y, sf.y), 0.f);
                    hd.z = fmaxf(fmaf(hd.z, sc.z, sf.z), 0.f);
                    hd.w = fmaxf(fmaf(hd.w, sc.w, sf.w), 0.f);
                }
                acc.x += hd.x; acc.y += hd.y; acc.z += hd.z; acc.w += hd.w;
            }
            u32 h0, l0, h1, l1;
            split2(acc.x, acc.y, h0, l0);
            split2(acc.z, acc.w, h1, l1);
            *(ull*)(sm + KA_A_HI + r * 272 + lane * 8) = (ull)h0 | ((ull)h1 << 32);
            *(ull*)(sm + KA_A_LO + r * 272 + lane * 8) = (ull)l0 | ((ull)l1 << 32);
        }
        gbar(bar);   // group's A rows ready (producers == consumers == this group)

        float acc[2][8][4];
#pragma unroll
        for (int a = 0; a < 2; a++)
#pragma unroll
            for (int b = 0; b < 8; b++)
#pragma unroll
                for (int c = 0; c < 4; c++) acc[a][b][c] = 0.f;

        for (int ks = 0; ks < 8; ks++) {
            const u32 ko = ks * 32;
            u32 ah[2][4], al[2][4];
#pragma unroll
            for (int mt = 0; mt < 2; mt++) {
                ldsm4(aHi + mt * (16 * 272) + ko, ah[mt][0], ah[mt][1], ah[mt][2], ah[mt][3]);
                ldsm4(aLo + mt * (16 * 272) + ko, al[mt][0], al[mt][1], al[mt][2], al[mt][3]);
            }
#pragma unroll
            for (int g = 0; g < 4; g++) {
                u32 bh0, bh1, bh2, bh3, bl0, bl1, bl2, bl3;
                ldsm4(bHi + g * (16 * 272) + ko, bh0, bh1, bh2, bh3);
                ldsm4(bLo + g * (16 * 272) + ko, bl0, bl1, bl2, bl3);
#pragma unroll
                for (int mt = 0; mt < 2; mt++) {
                    mma16816(acc[mt][2 * g],     ah[mt][0], ah[mt][1], ah[mt][2], ah[mt][3], bh0, bh2);
                    mma16816(acc[mt][2 * g + 1], ah[mt][0], ah[mt][1], ah[mt][2], ah[mt][3], bh1, bh3);
                    mma16816(acc[mt][2 * g],     ah[mt][0], ah[mt][1], ah[mt][2], ah[mt][3], bl0, bl2);
                    mma16816(acc[mt][2 * g + 1], ah[mt][0], ah[mt][1], ah[mt][2], ah[mt][3], bl1, bl3);
                    mma16816(acc[mt][2 * g],     al[mt][0], al[mt][1], al[mt][2], al[mt][3], bh0, bh2);
                    mma16816(acc[mt][2 * g + 1], al[mt][0], al[mt][1], al[mt][2], al[mt][3], bh1, bh3);
                }
            }
        }

        // epilogue: bias + relu + re-split -> interleaved (hi,lo) ull stores
        ull* hid64 = (ull*)(g_hid + (size_t)tile * 131072);
        const int m0 = wr * 32, n0 = wc * 64;
#pragma unroll
        for (int mt = 0; mt < 2; mt++)
#pragma unroll
            for (int nt = 0; nt < 8; nt++) {
                int col = n0 + nt * 8 + 2 * (lane & 3);
                int r0 = m0 + mt * 16 + (lane >> 2);
                float bv0 = bias[col], bv1 = bias[col + 1];
                u32 hp, lp;
                float v0 = fmaxf(acc[mt][nt][0] + bv0, 0.f);
                float v1 = fmaxf(acc[mt][nt][1] + bv1, 0.f);
                split2(v0, v1, hp, lp);
                hid64[r0 * 128 + (col >> 1)] = (ull)hp | ((ull)lp << 32);
                v0 = fmaxf(acc[mt][nt][2] + bv0, 0.f);
                v1 = fmaxf(acc[mt][nt][3] + bv1, 0.f);
                split2(v0, v1, hp, lp);
                hid64[(r0 + 8) * 128 + (col >> 1)] = (ull)hp | ((ull)lp << 32);
            }
        gbar(bar);   // group done reading A -> safe to overwrite next tile
    }
}

// ----------------- GEMM2: g_out = hidden @ W2 + b2, fused BN stats ----------
// smem: B hi/lo [128][528B], A hi/lo [128][272B] (half-K staged), bias[128]
#define KB_B_HI 0
#define KB_B_LO 67584
#define KB_A_HI 135168
#define KB_A_LO 169984
#define KB_BIAS 204800
#define KB_SMEM 205312

__global__ void __launch_bounds__(512, 1) kB(const float* __restrict__ b2, int layer) {
    extern __shared__ char sm[];
    u32 sb = smem_u32(sm);
    const int tid = threadIdx.x;
    const int warp = tid >> 5, lane = tid & 31;

    {
        const uint4* src = (const uint4*)g_w2T;
        for (int i = tid; i < 8192; i += 512) {
            int p = i >> 12, r = (i >> 5) & 127, w = i & 31;
            *(uint4*)(sm + KB_B_HI + p * 67584 + r * 528 + w * 16) =
                src[p * 4096 + r * 32 + w];
        }
        if (tid < 128) ((float*)(sm + KB_BIAS))[tid] = __ldg(b2 + tid);
    }
    __syncthreads();

    const int wr = warp >> 2, wc = warp & 3;        // 4 x 4 grid, 32x32 tiles
    const int bar = wr + 1;
    const int gt = tid & 127;                        // thread index within group
    const int R0 = wr * 32;                          // group's A-row base
    const u32 aHi = sb + KB_A_HI + (wr * 32 + (lane & 15)) * 272 + (lane >> 4) * 16;
    const u32 aLo = aHi + (KB_A_LO - KB_A_HI);
    const u32 bHi = sb + KB_B_HI + (wc * 32 + (lane & 15)) * 528 + (lane >> 4) * 16;
    const u32 bLo = bHi + 67584;
    const float* bias = (const float*)(sm + KB_BIAS);
    float* stats = g_stats + ((layer & 1) << 8);

    // BN stat accumulators: this thread's columns are fixed across tiles
    float st_s[4][2], st_s2[4][2];
#pragma unroll
    for (int nt = 0; nt < 4; nt++) {
        st_s[nt][0] = st_s[nt][1] = 0.f;
        st_s2[nt][0] = st_s2[nt][1] = 0.f;
    }

    for (int tile = blockIdx.x; tile < NT; tile += gridDim.x) {
        float acc[2][4][4];
#pragma unroll
        for (int a = 0; a < 2; a++)
#pragma unroll
            for (int b = 0; b < 4; b++)
#pragma unroll
                for (int c = 0; c < 4; c++) acc[a][b][c] = 0.f;

        const ull* hid64 = (const ull*)(g_hid + (size_t)tile * 131072);
        for (int pass = 0; pass < 2; pass++) {
            // stage group's own 32 A rows: de-interleave (hi,lo) -> planes
            for (int i = gt; i < 2048; i += 128) {
                int r = R0 + (i >> 6), cp = i & 63;
                ull v = __ldg(hid64 + r * 128 + pass * 64 + cp);
                *(u32*)(sm + KB_A_HI + r * 272 + cp * 4) = (u32)v;
                *(u32*)(sm + KB_A_LO + r * 272 + cp * 4) = (u32)(v >> 32);
            }
            gbar(bar);   // group's rows staged (producers == consumers)

            for (int ks = 0; ks < 8; ks++) {
                const u32 ko = ks * 32;
                const u32 bo = pass * 256 + ko;
                u32 ah[2][4], al[2][4];
#pragma unroll
                for (int mt = 0; mt < 2; mt++) {
                    ldsm4(aHi + mt * (16 * 272) + ko, ah[mt][0], ah[mt][1], ah[mt][2], ah[mt][3]);
                    ldsm4(aLo + mt * (16 * 272) + ko, al[mt][0], al[mt][1], al[mt][2], al[mt][3]);
                }
#pragma unroll
                for (int g = 0; g < 2; g++) {
                    u32 bh0, bh1, bh2, bh3, bl0, bl1, bl2, bl3;
                    ldsm4(bHi + g * (16 * 528) + bo, bh0, bh1, bh2, bh3);
                    ldsm4(bLo + g * (16 * 528) + bo, bl0, bl1, bl2, bl3);
#pragma unroll
                    for (int mt = 0; mt < 2; mt++) {
                        mma16816(acc[mt][2 * g],     ah[mt][0], ah[mt][1], ah[mt][2], ah[mt][3], bh0, bh2);
                        mma16816(acc[mt][2 * g + 1], ah[mt][0], ah[mt][1], ah[mt][2], ah[mt][3], bh1, bh3);
                        mma16816(acc[mt][2 * g],     ah[mt][0], ah[mt][1], ah[mt][2], ah[mt][3], bl0, bl2);
                        mma16816(acc[mt][2 * g + 1], ah[mt][0], ah[mt][1], ah[mt][2], ah[mt][3], bl1, bl3);
                        mma16816(acc[mt][2 * g],     al[mt][0], al[mt][1], al[mt][2], al[mt][3], bh0, bh2);
                        mma16816(acc[mt][2 * g + 1], al[mt][0], al[mt][1], al[mt][2], al[mt][3], bh1, bh3);
                    }
                }
            }
            gbar(bar);   // group done reading A -> safe to restage
        }

        // epilogue: bias, write fp32 g_out, accumulate BN stats in registers
        const int m0 = wr * 32, n0 = wc * 32;
#pragma unroll
        for (int mt = 0; mt < 2; mt++)
#pragma unroll
            for (int nt = 0; nt < 4; nt++) {
                int col = n0 + nt * 8 + 2 * (lane & 3);
                int r0 = tile * 128 + m0 + mt * 16 + (lane >> 2);
                float bv0 = bias[col], bv1 = bias[col + 1];
                if (r0 < N_NODES) {
                    float o0 = acc[mt][nt][0] + bv0;
                    float o1 = acc[mt][nt][1] + bv1;
                    *(float2*)(g_out + (size_t)r0 * D + col) = make_float2(o0, o1);
                    st_s[nt][0] += o0;  st_s2[nt][0] += o0 * o0;
                    st_s[nt][1] += o1;  st_s2[nt][1] += o1 * o1;
                }
                if (r0 + 8 < N_NODES) {
                    float o0 = acc[mt][nt][2] + bv0;
                    float o1 = acc[mt][nt][3] + bv1;
                    *(float2*)(g_out + (size_t)(r0 + 8) * D + col) = make_float2(o0, o1);
                    st_s[nt][0] += o0;  st_s2[nt][0] += o0 * o0;
                    st_s[nt][1] += o1;  st_s2[nt][1] += o1 * o1;
                }
            }
    }

    // reduce stats across the 8 lane-groups sharing columns (lane stride 4)
#pragma unroll
    for (int nt = 0; nt < 4; nt++)
#pragma unroll
        for (int p = 0; p < 2; p++) {
#pragma unroll
            for (int off = 16; off >= 4; off >>= 1) {
                st_s[nt][p]  += __shfl_xor_sync(0xffffffffu, st_s[nt][p],  off);
                st_s2[nt][p] += __shfl_xor_sync(0xffffffffu, st_s2[nt][p], off);
            }
        }
    if (lane < 4) {
        const int n0 = wc * 32;
#pragma unroll
        for (int nt = 0; nt < 4; nt++) {
            int col = n0 + nt * 8 + 2 * lane;
            atomicAdd(&stats[col],           st_s[nt][0]);
            atomicAdd(&stats[col + 1],       st_s[nt][1]);
            atomicAdd(&stats[128 + col],     st_s2[nt][0]);
            atomicAdd(&stats[128 + col + 1], st_s2[nt][1]);
        }
    }
}

// ----------------- final BN fold (last layer) -> g_aff ----------------------
__global__ void k_bnfold(const float* __restrict__ gamma, const float* __restrict__ beta) {
    int c = threadIdx.x;
    if (c < D) {
        const float* st = g_stats + (((NLAYERS - 1) & 1) << 8);
        float sum = st[c], sum2 = st[128 + c];
        const float invN = 1.0f / (float)N_NODES;
        float mean = sum * invN;
        float var = sum2 * invN - mean * mean;
        float scl = rsqrtf(var + 1e-5f) * __ldg(gamma + c);
        g_aff[c] = scl;
        g_aff[128 + c] = __ldg(beta + c) - mean * scl;
    }
}

// ----------------- final: apply last BN (no relu) -> d_out ------------------
__global__ void k_final(float* __restrict__ out) {
    int i = blockIdx.x * blockDim.x + threadIdx.x;
    if (i >= N_NODES * 32) return;
    int c0 = (i & 31) * 4;
    float4 v = ((const float4*)g_out)[i];
    float4 sc = *(const float4*)&g_aff[c0];
    float4 sf = *(const float4*)&g_aff[D + c0];
    v.x = fmaf(v.x, sc.x, sf.x);
    v.y = fmaf(v.y, sc.y, sf.y);
    v.z = fmaf(v.z, sc.z, sf.z);
    v.w = fmaf(v.w, sc.w, sf.w);
    ((float4*)out)[i] = v;
}

// ----------------- launch -----------------
extern "C" void kernel_launch(void* const* d_in, const int* in_sizes, int n_in,
                              void* d_out, int out_size) {
    const int*   x    = (const int*)d_in[0];
    const int*   ei   = (const int*)d_in[1];
    const int*   ea   = (const int*)d_in[2];
    const float* elem = (const float*)d_in[3];
    const float* chir = (const float*)d_in[4];
    const float* bt   = (const float*)d_in[5];
    const float* bd   = (const float*)d_in[6];
    const float* W1   = (const float*)d_in[7];
    const float* b1   = (const float*)d_in[8];
    const float* W2   = (const float*)d_in[9];
    const float* b2   = (const float*)d_in[10];
    const float* bng  = (const float*)d_in[11];
    const float* bnb  = (const float*)d_in[12];
    float* out = (float*)d_out;

    static int attr_done = 0;
    if (!attr_done) {
        cudaFuncSetAttribute(kA, cudaFuncAttributeMaxDynamicSharedMemorySize, KA_SMEM);
        cudaFuncSetAttribute(kB, cudaFuncAttributeMaxDynamicSharedMemorySize, KB_SMEM);
        attr_done = 1;
    }

    k_init<<<OFF_BLOCKS, 256>>>(x, bt, bd);
    k_setup<<<(N_NODES * 32 + 255) / 256, 256>>>(x, elem, chir, ei, W1, W2);
    k_offsets<<<OFF_BLOCKS, 256>>>();
    k_fill<<<(N_EDGES + 255) / 256, 256>>>(ei, ea);

    for (int l = 0; l < NLAYERS; l++) {
        const float* gm = bng + (l > 0 ? (l - 1) * D : 0);
        const float* bb = bnb + (l > 0 ? (l - 1) * D : 0);
        kA<<<148, 512, KA_SMEM>>>(b1, l, gm, bb);
        kB<<<148, 512, KB_SMEM>>>(b2, l);
    }
    k_bnfold<<<1, 128>>>(bng + (NLAYERS - 1) * D, bnb + (NLAYERS - 1) * D);
    k_final<<<(N_NODES * 32 + 255) / 256, 256>>>(out);
}

// round 16
// speedup vs baseline: 1.7956x; 1.1996x over previous
#include <cuda_runtime.h>

#define N_NODES 50000
#define N_EDGES 600000
#define D 128
#define NLAYERS 5
#define NT 391                    // ceil(50000/128) row tiles of 128
#define OFF_BLOCKS 196            // ceil(50000/256)

typedef unsigned long long ull;
typedef unsigned int u32;

// ----------------- persistent device scratch -----------------
__device__ float g_h[N_NODES * D];
__device__ float g_out[N_NODES * D];
__device__ float g_etab[9 * D];
__device__ float g_stats[2 * 256];     // double-buffered by layer parity
__device__ float g_aff[2 * D];
__device__ int   g_deg[N_NODES];
__device__ int   g_off[N_NODES];
__device__ int   g_cur[N_NODES];
__device__ int   g_csr[N_EDGES];
__device__ int   g_total;
__device__ int   g_is64;
// hidden activations per tile: [row(128)][colpair(128)] ull = (hi_u32 | lo_u32<<32)
__device__ __align__(16) unsigned char g_hid[(size_t)NT * 131072];
// weight images: [n][k] bf16, hi plane then lo plane (65536B each)
__device__ __align__(16) unsigned char g_w1T[131072];   // n=256, k=128
__device__ __align__(16) unsigned char g_w2T[131072];   // n=128, k=256

// ----------------- helpers -----------------
__device__ __forceinline__ u32 smem_u32(const void* p) {
    u32 a;
    asm("{ .reg .u64 t; cvta.to.shared.u64 t, %1; cvt.u32.u64 %0, t; }" : "=r"(a) : "l"(p));
    return a;
}
__device__ __forceinline__ void gbar(int id) {   // 128-thread named barrier
    asm volatile("bar.sync %0, 128;" :: "r"(id) : "memory");
}
// split two floats into hi-pair / lo-pair bf16x2 words (x0 -> low half)
__device__ __forceinline__ void split2(float x0, float x1, u32& hp, u32& lp) {
    asm("cvt.rn.bf16x2.f32 %0, %1, %2;" : "=r"(hp) : "f"(x1), "f"(x0));
    float h0 = __uint_as_float(hp << 16);
    float h1 = __uint_as_float(hp & 0xffff0000u);
    float r0 = x0 - h0, r1 = x1 - h1;
    asm("cvt.rn.bf16x2.f32 %0, %1, %2;" : "=r"(lp) : "f"(r1), "f"(r0));
}
__device__ __forceinline__ void ldsm4(u32 addr, u32& r0, u32& r1, u32& r2, u32& r3) {
    asm volatile("ldmatrix.sync.aligned.m8n8.x4.shared.b16 {%0,%1,%2,%3}, [%4];"
                 : "=r"(r0), "=r"(r1), "=r"(r2), "=r"(r3) : "r"(addr));
}
__device__ __forceinline__ void mma16816(float* c, u32 a0, u32 a1, u32 a2, u32 a3,
                                         u32 b0, u32 b1) {
    asm volatile(
        "mma.sync.aligned.m16n8k16.row.col.f32.bf16.bf16.f32 "
        "{%0,%1,%2,%3}, {%4,%5,%6,%7}, {%8,%9}, {%0,%1,%2,%3};"
        : "+f"(c[0]), "+f"(c[1]), "+f"(c[2]), "+f"(c[3])
        : "r"(a0), "r"(a1), "r"(a2), "r"(a3), "r"(b0), "r"(b1));
}

__device__ __forceinline__ int getidx(const int* __restrict__ p, int i) {
    return g_is64 ? p[2 * i] : p[i];
}

// ----------------- setup 1: zero(deg,stats,total) + detect + etab ------------
__global__ void k_init(const int* __restrict__ x,
                       const float* __restrict__ bt,
                       const float* __restrict__ bd) {
    int i = blockIdx.x * blockDim.x + threadIdx.x;
    if (i < N_NODES) g_deg[i] = 0;
    if (i < 512) g_stats[i] = 0.f;
    if (i == 0) g_total = 0;
    if (blockIdx.x == 12 && threadIdx.x == 0) {
        int nz = 0;
        for (int j = 1; j < 128; j += 2) nz |= x[j];
        g_is64 = (nz == 0) ? 1 : 0;
    }
    if (blockIdx.x >= 2 && blockIdx.x < 11 && threadIdx.x < 128) {
        int code = blockIdx.x - 2, t = code / 3, d = code % 3, c = threadIdx.x;
        g_etab[code * D + c] = bt[t * D + c] + bd[d * D + c];
    }
}

// ----------------- setup 2: embed + hist + weight prep (merged) --------------
__global__ void k_setup(const int* __restrict__ x,
                        const float* __restrict__ elem,
                        const float* __restrict__ chir,
                        const int* __restrict__ ei,
                        const float* __restrict__ W1,
                        const float* __restrict__ W2) {
    int i = blockIdx.x * blockDim.x + threadIdx.x;
    if (i < N_NODES * 32) {
        int node = i >> 5, l = i & 31;
        int a = getidx(x, 2 * node);
        int c = getidx(x, 2 * node + 1);
        float4 va = __ldg((const float4*)(elem + a * D) + l);
        float4 vc = __ldg((const float4*)(chir + c * D) + l);
        ((float4*)(g_h + node * D))[l] =
            make_float4(va.x + vc.x, va.y + vc.y, va.z + vc.z, va.w + vc.w);
    }
    if (i < N_EDGES) atomicAdd(&g_deg[getidx(ei, N_EDGES + i)], 1);
    if (i < 16384) {                          // W1: n 0..255, k pairs 0..63
        int n = i >> 6, kp = i & 63, k = kp * 2;
        float a = __ldg(W1 + k * 256 + n);
        float b = __ldg(W1 + (k + 1) * 256 + n);
        u32 hp, lp; split2(a, b, hp, lp);
        ((u32*)g_w1T)[n * 64 + kp] = hp;
        ((u32*)g_w1T)[16384 + n * 64 + kp] = lp;
    } else if (i < 32768) {                   // W2: n 0..127, k pairs 0..127
        int q = i - 16384;
        int n = q >> 7, kp = q & 127, k = kp * 2;
        float a = __ldg(W2 + k * 128 + n);
        float b = __ldg(W2 + (k + 1) * 128 + n);
        u32 hp, lp; split2(a, b, hp, lp);
        ((u32*)g_w2T)[n * 128 + kp] = hp;
        ((u32*)g_w2T)[16384 + n * 128 + kp] = lp;
    }
}

// ----------------- offsets: block-local scan + atomic base -------------------
__global__ void k_offsets() {
    __shared__ int sh[256];
    __shared__ int base_s;
    int tid = threadIdx.x;
    int i = blockIdx.x * 256 + tid;
    int v = (i < N_NODES) ? g_deg[i] : 0;
    sh[tid] = v;
    __syncthreads();
    for (int off = 1; off < 256; off <<= 1) {
        int t = (tid >= off) ? sh[tid - off] : 0;
        __syncthreads();
        sh[tid] += t;
        __syncthreads();
    }
    if (tid == 255) base_s = atomicAdd(&g_total, sh[255]);
    __syncthreads();
    if (i < N_NODES) {
        int ex = base_s + sh[tid] - v;
        g_off[i] = ex;
        g_cur[i] = ex;
    }
}

__global__ void k_fill(const int* __restrict__ ei, const int* __restrict__ ea) {
    int e = blockIdx.x * blockDim.x + threadIdx.x;
    if (e < N_EDGES) {
        int src = getidx(ei, e);
        int dst = getidx(ei, N_EDGES + e);
        int t = getidx(ea, 2 * e);
        int d = getidx(ea, 2 * e + 1);
        int pos = atomicAdd(&g_cur[dst], 1);
        g_csr[pos] = src | ((t * 3 + d) << 20);
    }
}

// ----------------- fused agg + GEMM1 (+ in-kernel BN fold), 1024 thr ---------
// smem: B hi/lo [256][272B], A hi/lo [128][272B], bias[256], etab[9*128], aff[256]
#define KA_B_HI 0
#define KA_B_LO 69632
#define KA_A_HI 139264
#define KA_A_LO 174080
#define KA_BIAS 208896
#define KA_ETAB 209920
#define KA_AFF  214528
#define KA_SMEM 215552

__device__ __forceinline__ void agg_one(float4& acc, float4 hv, const float* et,
                                        int code, int c0, int mode,
                                        float4 sc, float4 sf) {
    if (mode) {
        hv.x = fmaxf(fmaf(hv.x, sc.x, sf.x), 0.f);
        hv.y = fmaxf(fmaf(hv.y, sc.y, sf.y), 0.f);
        hv.z = fmaxf(fmaf(hv.z, sc.z, sf.z), 0.f);
        hv.w = fmaxf(fmaf(hv.w, sc.w, sf.w), 0.f);
    }
    float4 ev = *(const float4*)(et + code * D + c0);
    acc.x += fmaxf(hv.x + ev.x, 0.f);
    acc.y += fmaxf(hv.y + ev.y, 0.f);
    acc.z += fmaxf(hv.z + ev.z, 0.f);
    acc.w += fmaxf(hv.w + ev.w, 0.f);
}

__global__ void __launch_bounds__(1024, 1) kA(const float* __restrict__ b1, int layer,
                                              const float* __restrict__ gamma,
                                              const float* __restrict__ beta) {
    extern __shared__ char sm[];
    u32 sb = smem_u32(sm);
    const int tid = threadIdx.x;
    const int warp = tid >> 5, lane = tid & 31;
    const int mode = (layer > 0);

    // stage weights + bias + etab + fold BN affine (once)
    {
        const uint4* src = (const uint4*)g_w1T;
        for (int i = tid; i < 8192; i += 1024) {
            int p = i >> 12, r = (i >> 4) & 255, w = i & 15;
            *(uint4*)(sm + KA_B_HI + p * 69632 + r * 272 + w * 16) =
                src[p * 4096 + r * 16 + w];
        }
        if (tid < 256) ((float*)(sm + KA_BIAS))[tid] = __ldg(b1 + tid);
        for (int i = tid; i < 9 * D; i += 1024)
            ((float*)(sm + KA_ETAB))[i] = g_etab[i];
        if (mode && tid < 128) {
            const float* st = g_stats + (((layer - 1) & 1) << 8);
            float sum = st[tid], sum2 = st[128 + tid];
            const float invN = 1.0f / (float)N_NODES;
            float mean = sum * invN;
            float var = sum2 * invN - mean * mean;
            float scl = rsqrtf(var + 1e-5f) * __ldg(gamma + tid);
            ((float*)(sm + KA_AFF))[tid] = scl;
            ((float*)(sm + KA_AFF))[128 + tid] = __ldg(beta + tid) - mean * scl;
        }
        if (tid < 256) g_stats[((layer & 1) << 8) + tid] = 0.f;
    }
    __syncthreads();

    const float* __restrict__ in = mode ? g_out : g_h;
    const float* et = (const float*)(sm + KA_ETAB);
    const int c0 = lane * 4;

    float4 sc = make_float4(1.f, 1.f, 1.f, 1.f);
    float4 sf = make_float4(0.f, 0.f, 0.f, 0.f);
    if (mode) {
        sc = *(const float4*)((const float*)(sm + KA_AFF) + c0);
        sf = *(const float4*)((const float*)(sm + KA_AFF) + D + c0);
    }

    const int wr = warp >> 2, wc = warp & 3;        // 8 x 4 warp grid, 16x64 tiles
    const int bar = wr + 1;                          // group-local named barrier 1..8
    const u32 aHi = sb + KA_A_HI + (wr * 16 + (lane & 15)) * 272 + (lane >> 4) * 16;
    const u32 aLo = aHi + (KA_A_LO - KA_A_HI);
    const u32 bHi = sb + KA_B_HI + (wc * 64 + (lane & 15)) * 272 + (lane >> 4) * 16;
    const u32 bLo = bHi + 69632;
    const float* bias = (const float*)(sm + KA_BIAS);

    for (int tile = blockIdx.x; tile < NT; tile += gridDim.x) {
        // fused aggregation: each warp aggregates its 4 rows into smem A
#pragma unroll 1
        for (int r8 = 0; r8 < 4; r8++) {
            int r = warp * 4 + r8;
            int node = tile * 128 + r;
            float4 acc = make_float4(0.f, 0.f, 0.f, 0.f);
            if (node < N_NODES) {
                int beg = g_off[node];
                int end = beg + g_deg[node];
                int e = beg;
                for (; e + 4 <= end; e += 4) {
                    int v0 = __ldg(g_csr + e);
                    int v1 = __ldg(g_csr + e + 1);
                    int v2 = __ldg(g_csr + e + 2);
                    int v3 = __ldg(g_csr + e + 3);
                    float4 h0 = __ldg((const float4*)(in + (size_t)(v0 & 0xFFFFF) * D) + lane);
                    float4 h1 = __ldg((const float4*)(in + (size_t)(v1 & 0xFFFFF) * D) + lane);
                    float4 h2 = __ldg((const float4*)(in + (size_t)(v2 & 0xFFFFF) * D) + lane);
                    float4 h3 = __ldg((const float4*)(in + (size_t)(v3 & 0xFFFFF) * D) + lane);
                    agg_one(acc, h0, et, v0 >> 20, c0, mode, sc, sf);
                    agg_one(acc, h1, et, v1 >> 20, c0, mode, sc, sf);
                    agg_one(acc, h2, et, v2 >> 20, c0, mode, sc, sf);
                    agg_one(acc, h3, et, v3 >> 20, c0, mode, sc, sf);
                }
                for (; e < end; e++) {
                    int v = __ldg(g_csr + e);
                    float4 hv = __ldg((const float4*)(in + (size_t)(v & 0xFFFFF) * D) + lane);
                    agg_one(acc, hv, et, v >> 20, c0, mode, sc, sf);
                }
                float4 hd = __ldg((const float4*)(in + (size_t)node * D) + lane);
                if (mode) {
                    hd.x = fmaxf(fmaf(hd.x, sc.x, sf.x), 0.f);
                    hd.y = fmaxf(fmaf(hd.y, sc.y, sf.y), 0.f);
                    hd.z = fmaxf(fmaf(hd.z, sc.z, sf.z), 0.f);
                    hd.w = fmaxf(fmaf(hd.w, sc.w, sf.w), 0.f);
                }
                acc.x += hd.x; acc.y += hd.y; acc.z += hd.z; acc.w += hd.w;
            }
            u32 h0, l0, h1, l1;
            split2(acc.x, acc.y, h0, l0);
            split2(acc.z, acc.w, h1, l1);
            *(ull*)(sm + KA_A_HI + r * 272 + lane * 8) = (ull)h0 | ((ull)h1 << 32);
            *(ull*)(sm + KA_A_LO + r * 272 + lane * 8) = (ull)l0 | ((ull)l1 << 32);
        }
        gbar(bar);   // group's 16 A rows ready (producers == consumers == group)

        float acc[8][4];
#pragma unroll
        for (int b = 0; b < 8; b++)
#pragma unroll
            for (int c = 0; c < 4; c++) acc[b][c] = 0.f;

        for (int ks = 0; ks < 8; ks++) {
            const u32 ko = ks * 32;
            u32 ah[4], al[4];
            ldsm4(aHi + ko, ah[0], ah[1], ah[2], ah[3]);
            ldsm4(aLo + ko, al[0], al[1], al[2], al[3]);
#pragma unroll
            for (int g = 0; g < 4; g++) {
                u32 bh0, bh1, bh2, bh3, bl0, bl1, bl2, bl3;
                ldsm4(bHi + g * (16 * 272) + ko, bh0, bh1, bh2, bh3);
                ldsm4(bLo + g * (16 * 272) + ko, bl0, bl1, bl2, bl3);
                mma16816(acc[2 * g],     ah[0], ah[1], ah[2], ah[3], bh0, bh2);
                mma16816(acc[2 * g + 1], ah[0], ah[1], ah[2], ah[3], bh1, bh3);
                mma16816(acc[2 * g],     ah[0], ah[1], ah[2], ah[3], bl0, bl2);
                mma16816(acc[2 * g + 1], ah[0], ah[1], ah[2], ah[3], bl1, bl3);
                mma16816(acc[2 * g],     al[0], al[1], al[2], al[3], bh0, bh2);
                mma16816(acc[2 * g + 1], al[0], al[1], al[2], al[3], bh1, bh3);
            }
        }

        // epilogue: bias + relu + re-split -> interleaved (hi,lo) ull stores
        ull* hid64 = (ull*)(g_hid + (size_t)tile * 131072);
        const int m0 = wr * 16, n0 = wc * 64;
#pragma unroll
        for (int nt = 0; nt < 8; nt++) {
            int col = n0 + nt * 8 + 2 * (lane & 3);
            int r0 = m0 + (lane >> 2);
            float bv0 = bias[col], bv1 = bias[col + 1];
            u32 hp, lp;
            float v0 = fmaxf(acc[nt][0] + bv0, 0.f);
            float v1 = fmaxf(acc[nt][1] + bv1, 0.f);
            split2(v0, v1, hp, lp);
            hid64[r0 * 128 + (col >> 1)] = (ull)hp | ((ull)lp << 32);
            v0 = fmaxf(acc[nt][2] + bv0, 0.f);
            v1 = fmaxf(acc[nt][3] + bv1, 0.f);
            split2(v0, v1, hp, lp);
            hid64[(r0 + 8) * 128 + (col >> 1)] = (ull)hp | ((ull)lp << 32);
        }
        gbar(bar);   // group done reading A -> safe to overwrite next tile
    }
}

// ----------------- GEMM2: g_out = hidden @ W2 + b2, fused BN stats, 1024 thr -
// smem: B hi/lo [128][528B], A hi/lo [128][272B] (half-K staged), bias[128]
#define KB_B_HI 0
#define KB_B_LO 67584
#define KB_A_HI 135168
#define KB_A_LO 169984
#define KB_BIAS 204800
#define KB_SMEM 205312

__global__ void __launch_bounds__(1024, 1) kB(const float* __restrict__ b2, int layer) {
    extern __shared__ char sm[];
    u32 sb = smem_u32(sm);
    const int tid = threadIdx.x;
    const int warp = tid >> 5, lane = tid & 31;

    {
        const uint4* src = (const uint4*)g_w2T;
        for (int i = tid; i < 8192; i += 1024) {
            int p = i >> 12, r = (i >> 5) & 127, w = i & 31;
            *(uint4*)(sm + KB_B_HI + p * 67584 + r * 528 + w * 16) =
                src[p * 4096 + r * 32 + w];
        }
        if (tid < 128) ((float*)(sm + KB_BIAS))[tid] = __ldg(b2 + tid);
    }
    __syncthreads();

    const int wr = warp >> 2, wc = warp & 3;        // 8 x 4 grid, 16x32 tiles
    const int bar = wr + 1;
    const int gt = tid & 127;                        // thread index within group
    const int R0 = wr * 16;                          // group's A-row base
    const u32 aHi = sb + KB_A_HI + (wr * 16 + (lane & 15)) * 272 + (lane >> 4) * 16;
    const u32 aLo = aHi + (KB_A_LO - KB_A_HI);
    const u32 bHi = sb + KB_B_HI + (wc * 32 + (lane & 15)) * 528 + (lane >> 4) * 16;
    const u32 bLo = bHi + 67584;
    const float* bias = (const float*)(sm + KB_BIAS);
    float* stats = g_stats + ((layer & 1) << 8);

    // BN stat accumulators: this thread's columns are fixed across tiles
    float st_s[4][2], st_s2[4][2];
#pragma unroll
    for (int nt = 0; nt < 4; nt++) {
        st_s[nt][0] = st_s[nt][1] = 0.f;
        st_s2[nt][0] = st_s2[nt][1] = 0.f;
    }

    for (int tile = blockIdx.x; tile < NT; tile += gridDim.x) {
        float acc[4][4];
#pragma unroll
        for (int b = 0; b < 4; b++)
#pragma unroll
            for (int c = 0; c < 4; c++) acc[b][c] = 0.f;

        const ull* hid64 = (const ull*)(g_hid + (size_t)tile * 131072);
        for (int pass = 0; pass < 2; pass++) {
            // stage group's own 16 A rows: de-interleave (hi,lo) -> planes
            for (int i = gt; i < 1024; i += 128) {
                int r = R0 + (i >> 6), cp = i & 63;
                ull v = __ldg(hid64 + r * 128 + pass * 64 + cp);
                *(u32*)(sm + KB_A_HI + r * 272 + cp * 4) = (u32)v;
                *(u32*)(sm + KB_A_LO + r * 272 + cp * 4) = (u32)(v >> 32);
            }
            gbar(bar);   // group's rows staged (producers == consumers)

            for (int ks = 0; ks < 8; ks++) {
                const u32 ko = ks * 32;
                const u32 bo = pass * 256 + ko;
                u32 ah[4], al[4];
                ldsm4(aHi + ko, ah[0], ah[1], ah[2], ah[3]);
                ldsm4(aLo + ko, al[0], al[1], al[2], al[3]);
#pragma unroll
                for (int g = 0; g < 2; g++) {
                    u32 bh0, bh1, bh2, bh3, bl0, bl1, bl2, bl3;
                    ldsm4(bHi + g * (16 * 528) + bo, bh0, bh1, bh2, bh3);
                    ldsm4(bLo + g * (16 * 528) + bo, bl0, bl1, bl2, bl3);
                    mma16816(acc[2 * g],     ah[0], ah[1], ah[2], ah[3], bh0, bh2);
                    mma16816(acc[2 * g + 1], ah[0], ah[1], ah[2], ah[3], bh1, bh3);
                    mma16816(acc[2 * g],     ah[0], ah[1], ah[2], ah[3], bl0, bl2);
                    mma16816(acc[2 * g + 1], ah[0], ah[1], ah[2], ah[3], bl1, bl3);
                    mma16816(acc[2 * g],     al[0], al[1], al[2], al[3], bh0, bh2);
                    mma16816(acc[2 * g + 1], al[0], al[1], al[2], al[3], bh1, bh3);
                }
            }
            gbar(bar);   // group done reading A -> safe to restage
        }

        // epilogue: bias, write fp32 g_out, accumulate BN stats in registers
        const int m0 = wr * 16, n0 = wc * 32;
#pragma unroll
        for (int nt = 0; nt < 4; nt++) {
            int col = n0 + nt * 8 + 2 * (lane & 3);
            int r0 = tile * 128 + m0 + (lane >> 2);
            float bv0 = bias[col], bv1 = bias[col + 1];
            if (r0 < N_NODES) {
                float o0 = acc[nt][0] + bv0;
                float o1 = acc[nt][1] + bv1;
                *(float2*)(g_out + (size_t)r0 * D + col) = make_float2(o0, o1);
                st_s[nt][0] += o0;  st_s2[nt][0] += o0 * o0;
                st_s[nt][1] += o1;  st_s2[nt][1] += o1 * o1;
            }
            if (r0 + 8 < N_NODES) {
                float o0 = acc[nt][2] + bv0;
                float o1 = acc[nt][3] + bv1;
                *(float2*)(g_out + (size_t)(r0 + 8) * D + col) = make_float2(o0, o1);
                st_s[nt][0] += o0;  st_s2[nt][0] += o0 * o0;
                st_s[nt][1] += o1;  st_s2[nt][1] += o1 * o1;
            }
        }
    }

    // reduce stats across the 8 lane-groups sharing columns (lane stride 4)
#pragma unroll
    for (int nt = 0; nt < 4; nt++)
#pragma unroll
        for (int p = 0; p < 2; p++) {
#pragma unroll
            for (int off = 16; off >= 4; off >>= 1) {
                st_s[nt][p]  += __shfl_xor_sync(0xffffffffu, st_s[nt][p],  off);
                st_s2[nt][p] += __shfl_xor_sync(0xffffffffu, st_s2[nt][p], off);
            }
        }
    if (lane < 4) {
        const int n0 = wc * 32;
#pragma unroll
        for (int nt = 0; nt < 4; nt++) {
            int col = n0 + nt * 8 + 2 * lane;
            atomicAdd(&stats[col],           st_s[nt][0]);
            atomicAdd(&stats[col + 1],       st_s[nt][1]);
            atomicAdd(&stats[128 + col],     st_s2[nt][0]);
            atomicAdd(&stats[128 + col + 1], st_s2[nt][1]);
        }
    }
}

// ----------------- final BN fold (last layer) -> g_aff ----------------------
__global__ void k_bnfold(const float* __restrict__ gamma, const float* __restrict__ beta) {
    int c = threadIdx.x;
    if (c < D) {
        const float* st = g_stats + (((NLAYERS - 1) & 1) << 8);
        float sum = st[c], sum2 = st[128 + c];
        const float invN = 1.0f / (float)N_NODES;
        float mean = sum * invN;
        float var = sum2 * invN - mean * mean;
        float scl = rsqrtf(var + 1e-5f) * __ldg(gamma + c);
        g_aff[c] = scl;
        g_aff[128 + c] = __ldg(beta + c) - mean * scl;
    }
}

// ----------------- final: apply last BN (no relu) -> d_out ------------------
__global__ void k_final(float* __restrict__ out) {
    int i = blockIdx.x * blockDim.x + threadIdx.x;
    if (i >= N_NODES * 32) return;
    int c0 = (i & 31) * 4;
    float4 v = ((const float4*)g_out)[i];
    float4 sc = *(const float4*)&g_aff[c0];
    float4 sf = *(const float4*)&g_aff[D + c0];
    v.x = fmaf(v.x, sc.x, sf.x);
    v.y = fmaf(v.y, sc.y, sf.y);
    v.z = fmaf(v.z, sc.z, sf.z);
    v.w = fmaf(v.w, sc.w, sf.w);
    ((float4*)out)[i] = v;
}

// ----------------- launch -----------------
extern "C" void kernel_launch(void* const* d_in, const int* in_sizes, int n_in,
                              void* d_out, int out_size) {
    const int*   x    = (const int*)d_in[0];
    const int*   ei   = (const int*)d_in[1];
    const int*   ea   = (const int*)d_in[2];
    const float* elem = (const float*)d_in[3];
    const float* chir = (const float*)d_in[4];
    const float* bt   = (const float*)d_in[5];
    const float* bd   = (const float*)d_in[6];
    const float* W1   = (const float*)d_in[7];
    const float* b1   = (const float*)d_in[8];
    const float* W2   = (const float*)d_in[9];
    const float* b2   = (const float*)d_in[10];
    const float* bng  = (const float*)d_in[11];
    const float* bnb  = (const float*)d_in[12];
    float* out = (float*)d_out;

    static int attr_done = 0;
    if (!attr_done) {
        cudaFuncSetAttribute(kA, cudaFuncAttributeMaxDynamicSharedMemorySize, KA_SMEM);
        cudaFuncSetAttribute(kB, cudaFuncAttributeMaxDynamicSharedMemorySize, KB_SMEM);
        attr_done = 1;
    }

    k_init<<<OFF_BLOCKS, 256>>>(x, bt, bd);
    k_setup<<<(N_NODES * 32 + 255) / 256, 256>>>(x, elem, chir, ei, W1, W2);
    k_offsets<<<OFF_BLOCKS, 256>>>();
    k_fill<<<(N_EDGES + 255) / 256, 256>>>(ei, ea);

    for (int l = 0; l < NLAYERS; l++) {
        const float* gm = bng + (l > 0 ? (l - 1) * D : 0);
        const float* bb = bnb + (l > 0 ? (l - 1) * D : 0);
        kA<<<148, 1024, KA_SMEM>>>(b1, l, gm, bb);
        kB<<<148, 1024, KB_SMEM>>>(b2, l);
    }
    k_bnfold<<<1, 128>>>(bng + (NLAYERS - 1) * D, bnb + (NLAYERS - 1) * D);
    k_final<<<(N_NODES * 32 + 255) / 256, 256>>>(out);
}

// round 17
// speedup vs baseline: 1.7960x; 1.0002x over previous
#include <cuda_runtime.h>

#define N_NODES 50000
#define N_EDGES 600000
#define D 128
#define NLAYERS 5
#define NT 391                    // ceil(50000/128) row tiles of 128
#define OFF_BLOCKS 196            // ceil(50000/256)

typedef unsigned long long ull;
typedef unsigned int u32;

// ----------------- persistent device scratch -----------------
__device__ float g_h[N_NODES * D];
__device__ float g_out[N_NODES * D];
__device__ float g_etab[9 * D];
__device__ float g_stats[2 * 256];     // double-buffered by layer parity
__device__ float g_aff[2 * D];
__device__ int   g_deg[N_NODES];
__device__ int   g_off[N_NODES];
__device__ int   g_cur[N_NODES];
__device__ int   g_csr[N_EDGES];
__device__ int   g_total;
__device__ int   g_is64;
// hidden activations per tile: [row(128)][colpair(128)] ull = (hi_u32 | lo_u32<<32)
__device__ __align__(16) unsigned char g_hid[(size_t)NT * 131072];
// weight images: [n][k] bf16, hi plane then lo plane (65536B each)
__device__ __align__(16) unsigned char g_w1T[131072];   // n=256, k=128
__device__ __align__(16) unsigned char g_w2T[131072];   // n=128, k=256

// ----------------- helpers -----------------
__device__ __forceinline__ u32 smem_u32(const void* p) {
    u32 a;
    asm("{ .reg .u64 t; cvta.to.shared.u64 t, %1; cvt.u32.u64 %0, t; }" : "=r"(a) : "l"(p));
    return a;
}
__device__ __forceinline__ void gbar(int id) {   // 128-thread named barrier
    asm volatile("bar.sync %0, 128;" :: "r"(id) : "memory");
}
// split two floats into hi-pair / lo-pair bf16x2 words (x0 -> low half)
__device__ __forceinline__ void split2(float x0, float x1, u32& hp, u32& lp) {
    asm("cvt.rn.bf16x2.f32 %0, %1, %2;" : "=r"(hp) : "f"(x1), "f"(x0));
    float h0 = __uint_as_float(hp << 16);
    float h1 = __uint_as_float(hp & 0xffff0000u);
    float r0 = x0 - h0, r1 = x1 - h1;
    asm("cvt.rn.bf16x2.f32 %0, %1, %2;" : "=r"(lp) : "f"(r1), "f"(r0));
}
__device__ __forceinline__ void ldsm4(u32 addr, u32& r0, u32& r1, u32& r2, u32& r3) {
    asm volatile("ldmatrix.sync.aligned.m8n8.x4.shared.b16 {%0,%1,%2,%3}, [%4];"
                 : "=r"(r0), "=r"(r1), "=r"(r2), "=r"(r3) : "r"(addr));
}
__device__ __forceinline__ void mma16816(float* c, u32 a0, u32 a1, u32 a2, u32 a3,
                                         u32 b0, u32 b1) {
    asm volatile(
        "mma.sync.aligned.m16n8k16.row.col.f32.bf16.bf16.f32 "
        "{%0,%1,%2,%3}, {%4,%5,%6,%7}, {%8,%9}, {%0,%1,%2,%3};"
        : "+f"(c[0]), "+f"(c[1]), "+f"(c[2]), "+f"(c[3])
        : "r"(a0), "r"(a1), "r"(a2), "r"(a3), "r"(b0), "r"(b1));
}

__device__ __forceinline__ int getidx(const int* __restrict__ p, int i) {
    return g_is64 ? p[2 * i] : p[i];
}

// ----------------- setup 1: zero(deg,stats,total) + detect + etab ------------
__global__ void k_init(const int* __restrict__ x,
                       const float* __restrict__ bt,
                       const float* __restrict__ bd) {
    int i = blockIdx.x * blockDim.x + threadIdx.x;
    if (i < N_NODES) g_deg[i] = 0;
    if (i < 512) g_stats[i] = 0.f;
    if (i == 0) g_total = 0;
    if (blockIdx.x == 12 && threadIdx.x == 0) {
        int nz = 0;
        for (int j = 1; j < 128; j += 2) nz |= x[j];
        g_is64 = (nz == 0) ? 1 : 0;
    }
    if (blockIdx.x >= 2 && blockIdx.x < 11 && threadIdx.x < 128) {
        int code = blockIdx.x - 2, t = code / 3, d = code % 3, c = threadIdx.x;
        g_etab[code * D + c] = bt[t * D + c] + bd[d * D + c];
    }
}

// ----------------- setup 2: embed + hist + weight prep (merged) --------------
__global__ void k_setup(const int* __restrict__ x,
                        const float* __restrict__ elem,
                        const float* __restrict__ chir,
                        const int* __restrict__ ei,
                        const float* __restrict__ W1,
                        const float* __restrict__ W2) {
    int i = blockIdx.x * blockDim.x + threadIdx.x;
    if (i < N_NODES * 32) {
        int node = i >> 5, l = i & 31;
        int a = getidx(x, 2 * node);
        int c = getidx(x, 2 * node + 1);
        float4 va = __ldg((const float4*)(elem + a * D) + l);
        float4 vc = __ldg((const float4*)(chir + c * D) + l);
        ((float4*)(g_h + node * D))[l] =
            make_float4(va.x + vc.x, va.y + vc.y, va.z + vc.z, va.w + vc.w);
    }
    if (i < N_EDGES) atomicAdd(&g_deg[getidx(ei, N_EDGES + i)], 1);
    if (i < 16384) {                          // W1: n 0..255, k pairs 0..63
        int n = i >> 6, kp = i & 63, k = kp * 2;
        float a = __ldg(W1 + k * 256 + n);
        float b = __ldg(W1 + (k + 1) * 256 + n);
        u32 hp, lp; split2(a, b, hp, lp);
        ((u32*)g_w1T)[n * 64 + kp] = hp;
        ((u32*)g_w1T)[16384 + n * 64 + kp] = lp;
    } else if (i < 32768) {                   // W2: n 0..127, k pairs 0..127
        int q = i - 16384;
        int n = q >> 7, kp = q & 127, k = kp * 2;
        float a = __ldg(W2 + k * 128 + n);
        float b = __ldg(W2 + (k + 1) * 128 + n);
        u32 hp, lp; split2(a, b, hp, lp);
        ((u32*)g_w2T)[n * 128 + kp] = hp;
        ((u32*)g_w2T)[16384 + n * 128 + kp] = lp;
    }
}

// ----------------- offsets: block-local scan + atomic base -------------------
__global__ void k_offsets() {
    __shared__ int sh[256];
    __shared__ int base_s;
    int tid = threadIdx.x;
    int i = blockIdx.x * 256 + tid;
    int v = (i < N_NODES) ? g_deg[i] : 0;
    sh[tid] = v;
    __syncthreads();
    for (int off = 1; off < 256; off <<= 1) {
        int t = (tid >= off) ? sh[tid - off] : 0;
        __syncthreads();
        sh[tid] += t;
        __syncthreads();
    }
    if (tid == 255) base_s = atomicAdd(&g_total, sh[255]);
    __syncthreads();
    if (i < N_NODES) {
        int ex = base_s + sh[tid] - v;
        g_off[i] = ex;
        g_cur[i] = ex;
    }
}

__global__ void k_fill(const int* __restrict__ ei, const int* __restrict__ ea) {
    int e = blockIdx.x * blockDim.x + threadIdx.x;
    if (e < N_EDGES) {
        int src = getidx(ei, e);
        int dst = getidx(ei, N_EDGES + e);
        int t = getidx(ea, 2 * e);
        int d = getidx(ea, 2 * e + 1);
        int pos = atomicAdd(&g_cur[dst], 1);
        g_csr[pos] = src | ((t * 3 + d) << 20);
    }
}

// ----------------- fused agg + GEMM1 (+ in-kernel BN fold), 1024 thr ---------
// smem: B hi/lo [256][272B], A hi/lo [128][272B], bias[256], etab[9*128], aff[256]
#define KA_B_HI 0
#define KA_B_LO 69632
#define KA_A_HI 139264
#define KA_A_LO 174080
#define KA_BIAS 208896
#define KA_ETAB 209920
#define KA_AFF  214528
#define KA_SMEM 215552

__device__ __forceinline__ void agg_one(float4& acc, float4 hv, const float* et,
                                        int code, int c0, int mode,
                                        float4 sc, float4 sf) {
    if (mode) {
        hv.x = fmaxf(fmaf(hv.x, sc.x, sf.x), 0.f);
        hv.y = fmaxf(fmaf(hv.y, sc.y, sf.y), 0.f);
        hv.z = fmaxf(fmaf(hv.z, sc.z, sf.z), 0.f);
        hv.w = fmaxf(fmaf(hv.w, sc.w, sf.w), 0.f);
    }
    float4 ev = *(const float4*)(et + code * D + c0);
    acc.x += fmaxf(hv.x + ev.x, 0.f);
    acc.y += fmaxf(hv.y + ev.y, 0.f);
    acc.z += fmaxf(hv.z + ev.z, 0.f);
    acc.w += fmaxf(hv.w + ev.w, 0.f);
}

// 4 edges of one row: 4 csr loads + 4 gathers + 4 accumulates
__device__ __forceinline__ void agg4(float4& acc, int e, const float* __restrict__ in,
                                     const float* et, int c0, int lane, int mode,
                                     float4 sc, float4 sf) {
    int v0 = __ldg(g_csr + e);
    int v1 = __ldg(g_csr + e + 1);
    int v2 = __ldg(g_csr + e + 2);
    int v3 = __ldg(g_csr + e + 3);
    float4 h0 = __ldg((const float4*)(in + (size_t)(v0 & 0xFFFFF) * D) + lane);
    float4 h1 = __ldg((const float4*)(in + (size_t)(v1 & 0xFFFFF) * D) + lane);
    float4 h2 = __ldg((const float4*)(in + (size_t)(v2 & 0xFFFFF) * D) + lane);
    float4 h3 = __ldg((const float4*)(in + (size_t)(v3 & 0xFFFFF) * D) + lane);
    agg_one(acc, h0, et, v0 >> 20, c0, mode, sc, sf);
    agg_one(acc, h1, et, v1 >> 20, c0, mode, sc, sf);
    agg_one(acc, h2, et, v2 >> 20, c0, mode, sc, sf);
    agg_one(acc, h3, et, v3 >> 20, c0, mode, sc, sf);
}

__global__ void __launch_bounds__(1024, 1) kA(const float* __restrict__ b1, int layer,
                                              const float* __restrict__ gamma,
                                              const float* __restrict__ beta) {
    extern __shared__ char sm[];
    u32 sb = smem_u32(sm);
    const int tid = threadIdx.x;
    const int warp = tid >> 5, lane = tid & 31;
    const int mode = (layer > 0);

    // stage weights + bias + etab + fold BN affine (once)
    {
        const uint4* src = (const uint4*)g_w1T;
        for (int i = tid; i < 8192; i += 1024) {
            int p = i >> 12, r = (i >> 4) & 255, w = i & 15;
            *(uint4*)(sm + KA_B_HI + p * 69632 + r * 272 + w * 16) =
                src[p * 4096 + r * 16 + w];
        }
        if (tid < 256) ((float*)(sm + KA_BIAS))[tid] = __ldg(b1 + tid);
        for (int i = tid; i < 9 * D; i += 1024)
            ((float*)(sm + KA_ETAB))[i] = g_etab[i];
        if (mode && tid < 128) {
            const float* st = g_stats + (((layer - 1) & 1) << 8);
            float sum = st[tid], sum2 = st[128 + tid];
            const float invN = 1.0f / (float)N_NODES;
            float mean = sum * invN;
            float var = sum2 * invN - mean * mean;
            float scl = rsqrtf(var + 1e-5f) * __ldg(gamma + tid);
            ((float*)(sm + KA_AFF))[tid] = scl;
            ((float*)(sm + KA_AFF))[128 + tid] = __ldg(beta + tid) - mean * scl;
        }
        if (tid < 256) g_stats[((layer & 1) << 8) + tid] = 0.f;
    }
    __syncthreads();

    const float* __restrict__ in = mode ? g_out : g_h;
    const float* et = (const float*)(sm + KA_ETAB);
    const int c0 = lane * 4;

    float4 sc = make_float4(1.f, 1.f, 1.f, 1.f);
    float4 sf = make_float4(0.f, 0.f, 0.f, 0.f);
    if (mode) {
        sc = *(const float4*)((const float*)(sm + KA_AFF) + c0);
        sf = *(const float4*)((const float*)(sm + KA_AFF) + D + c0);
    }

    const int wr = warp >> 2, wc = warp & 3;        // 8 x 4 warp grid, 16x64 tiles
    const int bar = wr + 1;                          // group-local named barrier 1..8
    const u32 aHi = sb + KA_A_HI + (wr * 16 + (lane & 15)) * 272 + (lane >> 4) * 16;
    const u32 aLo = aHi + (KA_A_LO - KA_A_HI);
    const u32 bHi = sb + KA_B_HI + (wc * 64 + (lane & 15)) * 272 + (lane >> 4) * 16;
    const u32 bLo = bHi + 69632;
    const float* bias = (const float*)(sm + KA_BIAS);

    for (int tile = blockIdx.x; tile < NT; tile += gridDim.x) {
        // fused aggregation: warp's 4 rows as 2 concurrent pairs (MLP=8)
#pragma unroll 1
        for (int pr = 0; pr < 2; pr++) {
            int r0 = warp * 4 + pr * 2;
            int r1 = r0 + 1;
            int node0 = tile * 128 + r0;
            int node1 = node0 + 1;
            int e0 = 0, lim0 = 0, end0 = 0;
            int e1 = 0, lim1 = 0, end1 = 0;
            if (node0 < N_NODES) {
                e0 = g_off[node0];
                end0 = e0 + g_deg[node0];
                lim0 = e0 + ((end0 - e0) & ~3);
            }
            if (node1 < N_NODES) {
                e1 = g_off[node1];
                end1 = e1 + g_deg[node1];
                lim1 = e1 + ((end1 - e1) & ~3);
            }
            float4 acc0 = make_float4(0.f, 0.f, 0.f, 0.f);
            float4 acc1 = make_float4(0.f, 0.f, 0.f, 0.f);

            // paired main loop: 8 gathers in flight across 2 chains
            while (e0 < lim0 && e1 < lim1) {
                agg4(acc0, e0, in, et, c0, lane, mode, sc, sf);
                agg4(acc1, e1, in, et, c0, lane, mode, sc, sf);
                e0 += 4; e1 += 4;
            }
            while (e0 < lim0) { agg4(acc0, e0, in, et, c0, lane, mode, sc, sf); e0 += 4; }
            while (e1 < lim1) { agg4(acc1, e1, in, et, c0, lane, mode, sc, sf); e1 += 4; }
            for (; e0 < end0; e0++) {
                int v = __ldg(g_csr + e0);
                float4 hv = __ldg((const float4*)(in + (size_t)(v & 0xFFFFF) * D) + lane);
                agg_one(acc0, hv, et, v >> 20, c0, mode, sc, sf);
            }
            for (; e1 < end1; e1++) {
                int v = __ldg(g_csr + e1);
                float4 hv = __ldg((const float4*)(in + (size_t)(v & 0xFFFFF) * D) + lane);
                agg_one(acc1, hv, et, v >> 20, c0, mode, sc, sf);
            }

            if (node0 < N_NODES) {
                float4 hd = __ldg((const float4*)(in + (size_t)node0 * D) + lane);
                if (mode) {
                    hd.x = fmaxf(fmaf(hd.x, sc.x, sf.x), 0.f);
                    hd.y = fmaxf(fmaf(hd.y, sc.y, sf.y), 0.f);
                    hd.z = fmaxf(fmaf(hd.z, sc.z, sf.z), 0.f);
                    hd.w = fmaxf(fmaf(hd.w, sc.w, sf.w), 0.f);
                }
                acc0.x += hd.x; acc0.y += hd.y; acc0.z += hd.z; acc0.w += hd.w;
            }
            if (node1 < N_NODES) {
                float4 hd = __ldg((const float4*)(in + (size_t)node1 * D) + lane);
                if (mode) {
                    hd.x = fmaxf(fmaf(hd.x, sc.x, sf.x), 0.f);
                    hd.y = fmaxf(fmaf(hd.y, sc.y, sf.y), 0.f);
                    hd.z = fmaxf(fmaf(hd.z, sc.z, sf.z), 0.f);
                    hd.w = fmaxf(fmaf(hd.w, sc.w, sf.w), 0.f);
                }
                acc1.x += hd.x; acc1.y += hd.y; acc1.z += hd.z; acc1.w += hd.w;
            }

            u32 h0, l0, h1, l1;
            split2(acc0.x, acc0.y, h0, l0);
            split2(acc0.z, acc0.w, h1, l1);
            *(ull*)(sm + KA_A_HI + r0 * 272 + lane * 8) = (ull)h0 | ((ull)h1 << 32);
            *(ull*)(sm + KA_A_LO + r0 * 272 + lane * 8) = (ull)l0 | ((ull)l1 << 32);
            split2(acc1.x, acc1.y, h0, l0);
            split2(acc1.z, acc1.w, h1, l1);
            *(ull*)(sm + KA_A_HI + r1 * 272 + lane * 8) = (ull)h0 | ((ull)h1 << 32);
            *(ull*)(sm + KA_A_LO + r1 * 272 + lane * 8) = (ull)l0 | ((ull)l1 << 32);
        }
        gbar(bar);   // group's 16 A rows ready (producers == consumers == group)

        float acc[8][4];
#pragma unroll
        for (int b = 0; b < 8; b++)
#pragma unroll
            for (int c = 0; c < 4; c++) acc[b][c] = 0.f;

        for (int ks = 0; ks < 8; ks++) {
            const u32 ko = ks * 32;
            u32 ah[4], al[4];
            ldsm4(aHi + ko, ah[0], ah[1], ah[2], ah[3]);
            ldsm4(aLo + ko, al[0], al[1], al[2], al[3]);
#pragma unroll
            for (int g = 0; g < 4; g++) {
                u32 bh0, bh1, bh2, bh3, bl0, bl1, bl2, bl3;
                ldsm4(bHi + g * (16 * 272) + ko, bh0, bh1, bh2, bh3);
                ldsm4(bLo + g * (16 * 272) + ko, bl0, bl1, bl2, bl3);
                mma16816(acc[2 * g],     ah[0], ah[1], ah[2], ah[3], bh0, bh2);
                mma16816(acc[2 * g + 1], ah[0], ah[1], ah[2], ah[3], bh1, bh3);
                mma16816(acc[2 * g],     ah[0], ah[1], ah[2], ah[3], bl0, bl2);
                mma16816(acc[2 * g + 1], ah[0], ah[1], ah[2], ah[3], bl1, bl3);
                mma16816(acc[2 * g],     al[0], al[1], al[2], al[3], bh0, bh2);
                mma16816(acc[2 * g + 1], al[0], al[1], al[2], al[3], bh1, bh3);
            }
        }

        // epilogue: bias + relu + re-split -> interleaved (hi,lo) ull stores
        ull* hid64 = (ull*)(g_hid + (size_t)tile * 131072);
        const int m0 = wr * 16, n0 = wc * 64;
#pragma unroll
        for (int nt = 0; nt < 8; nt++) {
            int col = n0 + nt * 8 + 2 * (lane & 3);
            int r0 = m0 + (lane >> 2);
            float bv0 = bias[col], bv1 = bias[col + 1];
            u32 hp, lp;
            float v0 = fmaxf(acc[nt][0] + bv0, 0.f);
            float v1 = fmaxf(acc[nt][1] + bv1, 0.f);
            split2(v0, v1, hp, lp);
            hid64[r0 * 128 + (col >> 1)] = (ull)hp | ((ull)lp << 32);
            v0 = fmaxf(acc[nt][2] + bv0, 0.f);
            v1 = fmaxf(acc[nt][3] + bv1, 0.f);
            split2(v0, v1, hp, lp);
            hid64[(r0 + 8) * 128 + (col >> 1)] = (ull)hp | ((ull)lp << 32);
        }
        gbar(bar);   // group done reading A -> safe to overwrite next tile
    }
}

// ----------------- GEMM2: g_out = hidden @ W2 + b2, fused BN stats, 1024 thr -
// smem: B hi/lo [128][528B], A hi/lo [128][272B] (half-K staged), bias[128]
#define KB_B_HI 0
#define KB_B_LO 67584
#define KB_A_HI 135168
#define KB_A_LO 169984
#define KB_BIAS 204800
#define KB_SMEM 205312

__global__ void __launch_bounds__(1024, 1) kB(const float* __restrict__ b2, int layer) {
    extern __shared__ char sm[];
    u32 sb = smem_u32(sm);
    const int tid = threadIdx.x;
    const int warp = tid >> 5, lane = tid & 31;

    {
        const uint4* src = (const uint4*)g_w2T;
        for (int i = tid; i < 8192; i += 1024) {
            int p = i >> 12, r = (i >> 5) & 127, w = i & 31;
            *(uint4*)(sm + KB_B_HI + p * 67584 + r * 528 + w * 16) =
                src[p * 4096 + r * 32 + w];
        }
        if (tid < 128) ((float*)(sm + KB_BIAS))[tid] = __ldg(b2 + tid);
    }
    __syncthreads();

    const int wr = warp >> 2, wc = warp & 3;        // 8 x 4 grid, 16x32 tiles
    const int bar = wr + 1;
    const int gt = tid & 127;                        // thread index within group
    const int R0 = wr * 16;                          // group's A-row base
    const u32 aHi = sb + KB_A_HI + (wr * 16 + (lane & 15)) * 272 + (lane >> 4) * 16;
    const u32 aLo = aHi + (KB_A_LO - KB_A_HI);
    const u32 bHi = sb + KB_B_HI + (wc * 32 + (lane & 15)) * 528 + (lane >> 4) * 16;
    const u32 bLo = bHi + 67584;
    const float* bias = (const float*)(sm + KB_BIAS);
    float* stats = g_stats + ((layer & 1) << 8);

    // BN stat accumulators: this thread's columns are fixed across tiles
    float st_s[4][2], st_s2[4][2];
#pragma unroll
    for (int nt = 0; nt < 4; nt++) {
        st_s[nt][0] = st_s[nt][1] = 0.f;
        st_s2[nt][0] = st_s2[nt][1] = 0.f;
    }

    for (int tile = blockIdx.x; tile < NT; tile += gridDim.x) {
        float acc[4][4];
#pragma unroll
        for (int b = 0; b < 4; b++)
#pragma unroll
            for (int c = 0; c < 4; c++) acc[b][c] = 0.f;

        const ull* hid64 = (const ull*)(g_hid + (size_t)tile * 131072);
        for (int pass = 0; pass < 2; pass++) {
            // stage group's own 16 A rows: de-interleave (hi,lo) -> planes
            for (int i = gt; i < 1024; i += 128) {
                int r = R0 + (i >> 6), cp = i & 63;
                ull v = __ldg(hid64 + r * 128 + pass * 64 + cp);
                *(u32*)(sm + KB_A_HI + r * 272 + cp * 4) = (u32)v;
                *(u32*)(sm + KB_A_LO + r * 272 + cp * 4) = (u32)(v >> 32);
            }
            gbar(bar);   // group's rows staged (producers == consumers)

            for (int ks = 0; ks < 8; ks++) {
                const u32 ko = ks * 32;
                const u32 bo = pass * 256 + ko;
                u32 ah[4], al[4];
                ldsm4(aHi + ko, ah[0], ah[1], ah[2], ah[3]);
                ldsm4(aLo + ko, al[0], al[1], al[2], al[3]);
#pragma unroll
                for (int g = 0; g < 2; g++) {
                    u32 bh0, bh1, bh2, bh3, bl0, bl1, bl2, bl3;
                    ldsm4(bHi + g * (16 * 528) + bo, bh0, bh1, bh2, bh3);
                    ldsm4(bLo + g * (16 * 528) + bo, bl0, bl1, bl2, bl3);
                    mma16816(acc[2 * g],     ah[0], ah[1], ah[2], ah[3], bh0, bh2);
                    mma16816(acc[2 * g + 1], ah[0], ah[1], ah[2], ah[3], bh1, bh3);
                    mma16816(acc[2 * g],     ah[0], ah[1], ah[2], ah[3], bl0, bl2);
                    mma16816(acc[2 * g + 1], ah[0], ah[1], ah[2], ah[3], bl1, bl3);
                    mma16816(acc[2 * g],     al[0], al[1], al[2], al[3], bh0, bh2);
                    mma16816(acc[2 * g + 1], al[0], al[1], al[2], al[3], bh1, bh3);
                }
            }
            gbar(bar);   // group done reading A -> safe to restage
        }

        // epilogue: bias, write fp32 g_out, accumulate BN stats in registers
        const int m0 = wr * 16, n0 = wc * 32;
#pragma unroll
        for (int nt = 0; nt < 4; nt++) {
            int col = n0 + nt * 8 + 2 * (lane & 3);
            int r0 = tile * 128 + m0 + (lane >> 2);
            float bv0 = bias[col], bv1 = bias[col + 1];
            if (r0 < N_NODES) {
                float o0 = acc[nt][0] + bv0;
                float o1 = acc[nt][1] + bv1;
                *(float2*)(g_out + (size_t)r0 * D + col) = make_float2(o0, o1);
                st_s[nt][0] += o0;  st_s2[nt][0] += o0 * o0;
                st_s[nt][1] += o1;  st_s2[nt][1] += o1 * o1;
            }
            if (r0 + 8 < N_NODES) {
                float o0 = acc[nt][2] + bv0;
                float o1 = acc[nt][3] + bv1;
                *(float2*)(g_out + (size_t)(r0 + 8) * D + col) = make_float2(o0, o1);
                st_s[nt][0] += o0;  st_s2[nt][0] += o0 * o0;
                st_s[nt][1] += o1;  st_s2[nt][1] += o1 * o1;
            }
        }
    }

    // reduce stats across the 8 lane-groups sharing columns (lane stride 4)
#pragma unroll
    for (int nt = 0; nt < 4; nt++)
#pragma unroll
        for (int p = 0; p < 2; p++) {
#pragma unroll
            for (int off = 16; off >= 4; off >>= 1) {
                st_s[nt][p]  += __shfl_xor_sync(0xffffffffu, st_s[nt][p],  off);
                st_s2[nt][p] += __shfl_xor_sync(0xffffffffu, st_s2[nt][p], off);
            }
        }
    if (lane < 4) {
        const int n0 = wc * 32;
#pragma unroll
        for (int nt = 0; nt < 4; nt++) {
            int col = n0 + nt * 8 + 2 * lane;
            atomicAdd(&stats[col],           st_s[nt][0]);
            atomicAdd(&stats[col + 1],       st_s[nt][1]);
            atomicAdd(&stats[128 + col],     st_s2[nt][0]);
            atomicAdd(&stats[128 + col + 1], st_s2[nt][1]);
        }
    }
}

// ----------------- final BN fold (last layer) -> g_aff ----------------------
__global__ void k_bnfold(const float* __restrict__ gamma, const float* __restrict__ beta) {
    int c = threadIdx.x;
    if (c < D) {
        const float* st = g_stats + (((NLAYERS - 1) & 1) << 8);
        float sum = st[c], sum2 = st[128 + c];
        const float invN = 1.0f / (float)N_NODES;
        float mean = sum * invN;
        float var = sum2 * invN - mean * mean;
        float scl = rsqrtf(var + 1e-5f) * __ldg(gamma + c);
        g_aff[c] = scl;
        g_aff[128 + c] = __ldg(beta + c) - mean * scl;
    }
}

// ----------------- final: apply last BN (no relu) -> d_out ------------------
__global__ void k_final(float* __restrict__ out) {
    int i = blockIdx.x * blockDim.x + threadIdx.x;
    if (i >= N_NODES * 32) return;
    int c0 = (i & 31) * 4;
    float4 v = ((const float4*)g_out)[i];
    float4 sc = *(const float4*)&g_aff[c0];
    float4 sf = *(const float4*)&g_aff[D + c0];
    v.x = fmaf(v.x, sc.x, sf.x);
    v.y = fmaf(v.y, sc.y, sf.y);
    v.z = fmaf(v.z, sc.z, sf.z);
    v.w = fmaf(v.w, sc.w, sf.w);
    ((float4*)out)[i] = v;
}

// ----------------- launch -----------------
extern "C" void kernel_launch(void* const* d_in, const int* in_sizes, int n_in,
                              void* d_out, int out_size) {
    const int*   x    = (const int*)d_in[0];
    const int*   ei   = (const int*)d_in[1];
    const int*   ea   = (const int*)d_in[2];
    const float* elem = (const float*)d_in[3];
    const float* chir = (const float*)d_in[4];
    const float* bt   = (const float*)d_in[5];
    const float* bd   = (const float*)d_in[6];
    const float* W1   = (const float*)d_in[7];
    const float* b1   = (const float*)d_in[8];
    const float* W2   = (const float*)d_in[9];
    const float* b2   = (const float*)d_in[10];
    const float* bng  = (const float*)d_in[11];
    const float* bnb  = (const float*)d_in[12];
    float* out = (float*)d_out;

    static int attr_done = 0;
    if (!attr_done) {
        cudaFuncSetAttribute(kA, cudaFuncAttributeMaxDynamicSharedMemorySize, KA_SMEM);
        cudaFuncSetAttribute(kB, cudaFuncAttributeMaxDynamicSharedMemorySize, KB_SMEM);
        attr_done = 1;
    }

    k_init<<<OFF_BLOCKS, 256>>>(x, bt, bd);
    k_setup<<<(N_NODES * 32 + 255) / 256, 256>>>(x, elem, chir, ei, W1, W2);
    k_offsets<<<OFF_BLOCKS, 256>>>();
    k_fill<<<(N_EDGES + 255) / 256, 256>>>(ei, ea);

    for (int l = 0; l < NLAYERS; l++) {
        const float* gm = bng + (l > 0 ? (l - 1) * D : 0);
        const float* bb = bnb + (l > 0 ? (l - 1) * D : 0);
        kA<<<148, 1024, KA_SMEM>>>(b1, l, gm, bb);
        kB<<<148, 1024, KB_SMEM>>>(b2, l);
    }
    k_bnfold<<<1, 128>>>(bng + (NLAYERS - 1) * D, bnb + (NLAYERS - 1) * D);
    k_final<<<(N_NODES * 32 + 255) / 256, 256>>>(out);
}